// round 1
// baseline (speedup 1.0000x reference)
#include <cuda_runtime.h>
#include <cuda_bf16.h>
#include <math.h>

// ---------------------------------------------------------------------------
// Problem constants
// ---------------------------------------------------------------------------
#define Bsz   8
#define Tseq  1024
#define EMB   768
#define NH    12
#define HD    64
#define NTOK  (Bsz * Tseq)          // 8192
#define FFND  (4 * EMB)             // 3072

// ---------------------------------------------------------------------------
// Scratch (device globals — allocation-free)
// ---------------------------------------------------------------------------
__device__ float g_h  [NTOK * EMB];                 // LN output (reused for LN1 & LN2)
__device__ float g_q  [NTOK * EMB];                 // [B,H,T,D]
__device__ float g_k  [NTOK * EMB];                 // [B,H,T,D]
__device__ float g_vt [NTOK * EMB];                 // [B,H,D,T]
__device__ float g_sc [(long)Bsz * NH * Tseq * Tseq]; // scores / attn (in-place softmax)
__device__ float g_ctx[NTOK * EMB];                 // [B,T,E]
__device__ float g_x2 [NTOK * EMB];                 // residual after attention
__device__ float g_ffn[NTOK * FFND];                // gelu(h @ W1^T)

// ---------------------------------------------------------------------------
// Block reduction helpers (blockDim.x == 256)
// ---------------------------------------------------------------------------
__device__ __forceinline__ float blk_sum(float v, float* s) {
    int t = threadIdx.x;
    #pragma unroll
    for (int o = 16; o; o >>= 1) v += __shfl_xor_sync(0xffffffffu, v, o);
    if ((t & 31) == 0) s[t >> 5] = v;
    __syncthreads();
    if (t < 32) {
        float w = (t < 8) ? s[t] : 0.0f;
        #pragma unroll
        for (int o = 4; o; o >>= 1) w += __shfl_xor_sync(0xffffffffu, w, o);
        if (t == 0) s[0] = w;
    }
    __syncthreads();
    float r = s[0];
    __syncthreads();
    return r;
}

__device__ __forceinline__ float blk_max(float v, float* s) {
    int t = threadIdx.x;
    #pragma unroll
    for (int o = 16; o; o >>= 1) v = fmaxf(v, __shfl_xor_sync(0xffffffffu, v, o));
    if ((t & 31) == 0) s[t >> 5] = v;
    __syncthreads();
    if (t < 32) {
        float w = (t < 8) ? s[t] : -INFINITY;
        #pragma unroll
        for (int o = 4; o; o >>= 1) w = fmaxf(w, __shfl_xor_sync(0xffffffffu, w, o));
        if (t == 0) s[0] = w;
    }
    __syncthreads();
    float r = s[0];
    __syncthreads();
    return r;
}

// ---------------------------------------------------------------------------
// LayerNorm: one block per row of 768
// ---------------------------------------------------------------------------
__global__ void layernorm_k(const float* __restrict__ x, float* __restrict__ o,
                            const float* __restrict__ sc, const float* __restrict__ sh) {
    __shared__ float red[32];
    long row = blockIdx.x;
    const float* p = x + row * EMB;
    float* q = o + row * EMB;
    int t = threadIdx.x;
    float a0 = p[t], a1 = p[t + 256], a2 = p[t + 512];
    float mean = blk_sum(a0 + a1 + a2, red) * (1.0f / EMB);
    float d0 = a0 - mean, d1 = a1 - mean, d2 = a2 - mean;
    float var = blk_sum(d0 * d0 + d1 * d1 + d2 * d2, red) * (1.0f / EMB);
    float rstd = rsqrtf(var + 1e-5f);
    q[t      ] = d0 * rstd * sc[t      ] + sh[t      ];
    q[t + 256] = d1 * rstd * sc[t + 256] + sh[t + 256];
    q[t + 512] = d2 * rstd * sc[t + 512] + sh[t + 512];
}

// ---------------------------------------------------------------------------
// Row softmax over 1024 columns (in place). One block per row, 256 threads.
// ---------------------------------------------------------------------------
__global__ void softmax_k(float* __restrict__ S) {
    __shared__ float red[32];
    long row = blockIdx.x;
    float4* p = (float4*)(S + row * (long)Tseq);
    int t = threadIdx.x;
    float4 v = p[t];
    float m = blk_max(fmaxf(fmaxf(v.x, v.y), fmaxf(v.z, v.w)), red);
    float e0 = __expf(v.x - m), e1 = __expf(v.y - m);
    float e2 = __expf(v.z - m), e3 = __expf(v.w - m);
    float z = blk_sum(e0 + e1 + e2 + e3, red);
    float inv = 1.0f / z;
    p[t] = make_float4(e0 * inv, e1 * inv, e2 * inv, e3 * inv);
}

// ---------------------------------------------------------------------------
// Generic NT GEMM:  C[m,n] = sum_k A[m,k] * B[n,k]   (both row-major, K-contig)
// Tiling: BM=BN=64, BK=32, 16x16 threads, 4x4 microtile.
// Epilogues select output layout / fusion.
// ---------------------------------------------------------------------------
#define EPI_PLAIN  0
#define EPI_SCORES 1   // *0.125, causal mask, tile-level skip
#define EPI_QK     2   // scatter [tok,E] -> [B,H,T,D]
#define EPI_VT     3   // scatter [tok,E] -> [B,H,D,T]
#define EPI_CTX    4   // scatter per-(b,h) [T,D] -> [B,T,E]
#define EPI_RES    5   // + residual R (same layout as C)
#define EPI_GELU   6   // gelu(acc)

#define BM 64
#define BN 64
#define BK 32

__global__ void gemm_nt(const float* __restrict__ A, const float* __restrict__ Bm,
                        const float* __restrict__ R, float* __restrict__ C,
                        int M, int N, int K,
                        long sA, long sB, long sC, int epi) {
    int z = blockIdx.z;
    const float* Ab = A + (long)z * sA;
    const float* Bb = Bm + (long)z * sB;

    int bx = blockIdx.x, by = blockIdx.y;
    int row0 = by * BM, col0 = bx * BN;
    int tx = threadIdx.x, ty = threadIdx.y;
    int tid = ty * 16 + tx;

    if (epi == EPI_SCORES && bx > by) {
        // tile entirely above the causal diagonal: write mask value only
        float* Cp = C + (long)z * sC;
        for (int i = tid; i < BM * BN; i += 256) {
            int r = i >> 6, c = i & 63;
            Cp[(long)(row0 + r) * N + col0 + c] = -1e30f;
        }
        return;
    }

    __shared__ float As[BK][BM + 4];
    __shared__ float Bs[BK][BN + 4];

    float acc[4][4] = {};

    for (int k0 = 0; k0 < K; k0 += BK) {
        #pragma unroll
        for (int i = 0; i < 2; i++) {
            int idx = tid + i * 256;          // 512 float4 slots
            int r = idx >> 3;                 // 8 float4 per 32-wide row
            int cc = (idx & 7) * 4;
            float4 v = *(const float4*)&Ab[(long)(row0 + r) * K + k0 + cc];
            As[cc + 0][r] = v.x; As[cc + 1][r] = v.y;
            As[cc + 2][r] = v.z; As[cc + 3][r] = v.w;
        }
        #pragma unroll
        for (int i = 0; i < 2; i++) {
            int idx = tid + i * 256;
            int r = idx >> 3;
            int cc = (idx & 7) * 4;
            float4 v = *(const float4*)&Bb[(long)(col0 + r) * K + k0 + cc];
            Bs[cc + 0][r] = v.x; Bs[cc + 1][r] = v.y;
            Bs[cc + 2][r] = v.z; Bs[cc + 3][r] = v.w;
        }
        __syncthreads();
        #pragma unroll
        for (int k = 0; k < BK; k++) {
            float4 a = *(const float4*)&As[k][ty * 4];
            float4 b = *(const float4*)&Bs[k][tx * 4];
            acc[0][0] += a.x * b.x; acc[0][1] += a.x * b.y; acc[0][2] += a.x * b.z; acc[0][3] += a.x * b.w;
            acc[1][0] += a.y * b.x; acc[1][1] += a.y * b.y; acc[1][2] += a.y * b.z; acc[1][3] += a.y * b.w;
            acc[2][0] += a.z * b.x; acc[2][1] += a.z * b.y; acc[2][2] += a.z * b.z; acc[2][3] += a.z * b.w;
            acc[3][0] += a.w * b.x; acc[3][1] += a.w * b.y; acc[3][2] += a.w * b.z; acc[3][3] += a.w * b.w;
        }
        __syncthreads();
    }

    int r0 = row0 + ty * 4;
    int c0 = col0 + tx * 4;

    switch (epi) {
    case EPI_PLAIN: {
        float* Cp = C + (long)z * sC;
        #pragma unroll
        for (int i = 0; i < 4; i++)
            #pragma unroll
            for (int j = 0; j < 4; j++)
                Cp[(long)(r0 + i) * N + c0 + j] = acc[i][j];
        break; }
    case EPI_SCORES: {
        float* Cp = C + (long)z * sC;
        #pragma unroll
        for (int i = 0; i < 4; i++)
            #pragma unroll
            for (int j = 0; j < 4; j++) {
                float v = acc[i][j] * 0.125f;               // 1/sqrt(64)
                if (c0 + j > r0 + i) v = -1e30f;            // causal mask
                Cp[(long)(r0 + i) * N + c0 + j] = v;
            }
        break; }
    case EPI_QK: {
        #pragma unroll
        for (int i = 0; i < 4; i++) {
            int gm = r0 + i;
            int b = gm >> 10, t = gm & 1023;
            #pragma unroll
            for (int j = 0; j < 4; j++) {
                int gn = c0 + j;
                int h = gn >> 6, d = gn & 63;
                C[(((long)(b * NH + h) << 10) + t) * HD + d] = acc[i][j];
            }
        }
        break; }
    case EPI_VT: {
        #pragma unroll
        for (int i = 0; i < 4; i++) {
            int gm = r0 + i;
            int b = gm >> 10, t = gm & 1023;
            #pragma unroll
            for (int j = 0; j < 4; j++) {
                int gn = c0 + j;
                int h = gn >> 6, d = gn & 63;
                C[((long)(b * NH + h) * HD + d) * Tseq + t] = acc[i][j];
            }
        }
        break; }
    case EPI_CTX: {
        int b = z / NH, h = z % NH;
        #pragma unroll
        for (int i = 0; i < 4; i++)
            #pragma unroll
            for (int j = 0; j < 4; j++)
                C[((long)(b * Tseq + r0 + i)) * EMB + h * HD + c0 + j] = acc[i][j];
        break; }
    case EPI_RES: {
        #pragma unroll
        for (int i = 0; i < 4; i++)
            #pragma unroll
            for (int j = 0; j < 4; j++) {
                long o = (long)(r0 + i) * N + c0 + j;
                C[o] = acc[i][j] + R[o];
            }
        break; }
    case EPI_GELU: {
        const float cst = 0.7978845608028654f;
        #pragma unroll
        for (int i = 0; i < 4; i++)
            #pragma unroll
            for (int j = 0; j < 4; j++) {
                float u = acc[i][j];
                float g = 0.5f * u * (1.0f + tanhf(cst * (u + 0.044715f * u * u * u)));
                C[(long)(r0 + i) * N + c0 + j] = g;
            }
        break; }
    }
}

// ---------------------------------------------------------------------------
// Launch
// ---------------------------------------------------------------------------
extern "C" void kernel_launch(void* const* d_in, const int* in_sizes, int n_in,
                              void* d_out, int out_size) {
    const float* x    = (const float*)d_in[0];
    const float* wq   = (const float*)d_in[1];
    const float* wk   = (const float*)d_in[2];
    const float* wv   = (const float*)d_in[3];
    const float* wo   = (const float*)d_in[4];
    const float* w1   = (const float*)d_in[5];
    const float* w2   = (const float*)d_in[6];
    const float* ln1s = (const float*)d_in[7];
    const float* ln1b = (const float*)d_in[8];
    const float* ln2s = (const float*)d_in[9];
    const float* ln2b = (const float*)d_in[10];
    float* out = (float*)d_out;

    float *h, *q, *k, *vt, *sc, *ctx, *x2, *ffn;
    cudaGetSymbolAddress((void**)&h,   g_h);
    cudaGetSymbolAddress((void**)&q,   g_q);
    cudaGetSymbolAddress((void**)&k,   g_k);
    cudaGetSymbolAddress((void**)&vt,  g_vt);
    cudaGetSymbolAddress((void**)&sc,  g_sc);
    cudaGetSymbolAddress((void**)&ctx, g_ctx);
    cudaGetSymbolAddress((void**)&x2,  g_x2);
    cudaGetSymbolAddress((void**)&ffn, g_ffn);

    dim3 tb(16, 16);

    // 1) LN1
    layernorm_k<<<NTOK, 256>>>(x, h, ln1s, ln1b);

    // 2-4) QKV projections (fused reshape)
    gemm_nt<<<dim3(EMB / BN, NTOK / BM, 1), tb>>>(h, wq, nullptr, q,  NTOK, EMB, EMB, 0, 0, 0, EPI_QK);
    gemm_nt<<<dim3(EMB / BN, NTOK / BM, 1), tb>>>(h, wk, nullptr, k,  NTOK, EMB, EMB, 0, 0, 0, EPI_QK);
    gemm_nt<<<dim3(EMB / BN, NTOK / BM, 1), tb>>>(h, wv, nullptr, vt, NTOK, EMB, EMB, 0, 0, 0, EPI_VT);

    // 5) scores = QK^T/8 with causal mask; batched over B*H
    gemm_nt<<<dim3(Tseq / BN, Tseq / BM, Bsz * NH), tb>>>(
        q, k, nullptr, sc, Tseq, Tseq, HD,
        (long)Tseq * HD, (long)Tseq * HD, (long)Tseq * Tseq, EPI_SCORES);

    // 6) softmax rows
    softmax_k<<<Bsz * NH * Tseq, 256>>>(sc);

    // 7) ctx = attn @ V; batched, scatter to [B,T,E]
    gemm_nt<<<dim3(HD / BN, Tseq / BM, Bsz * NH), tb>>>(
        sc, vt, nullptr, ctx, Tseq, HD, Tseq,
        (long)Tseq * Tseq, (long)HD * Tseq, 0, EPI_CTX);

    // 8) x2 = x + ctx @ Wo^T
    gemm_nt<<<dim3(EMB / BN, NTOK / BM, 1), tb>>>(ctx, wo, x, x2, NTOK, EMB, EMB, 0, 0, 0, EPI_RES);

    // 9) LN2
    layernorm_k<<<NTOK, 256>>>(x2, h, ln2s, ln2b);

    // 10) ffn = gelu(h @ W1^T)
    gemm_nt<<<dim3(FFND / BN, NTOK / BM, 1), tb>>>(h, w1, nullptr, ffn, NTOK, FFND, EMB, 0, 0, 0, EPI_GELU);

    // 11) out = x2 + ffn @ W2^T
    gemm_nt<<<dim3(EMB / BN, NTOK / BM, 1), tb>>>(ffn, w2, x2, out, NTOK, EMB, FFND, 0, 0, 0, EPI_RES);
}

// round 2
// speedup vs baseline: 1.0009x; 1.0009x over previous
#include <cuda_runtime.h>
#include <cuda_bf16.h>
#include <math.h>

// ---------------------------------------------------------------------------
// Problem constants
// ---------------------------------------------------------------------------
#define Bsz   8
#define Tseq  1024
#define EMB   768
#define NH    12
#define HD    64
#define NTOK  (Bsz * Tseq)          // 8192
#define FFND  (4 * EMB)             // 3072

// ---------------------------------------------------------------------------
// Scratch (device globals — allocation-free)
// ---------------------------------------------------------------------------
__device__ float g_h  [NTOK * EMB];                 // LN output (reused for LN1 & LN2)
__device__ float g_q  [NTOK * EMB];                 // [B,H,T,D]
__device__ float g_k  [NTOK * EMB];                 // [B,H,T,D]
__device__ float g_vt [NTOK * EMB];                 // [B,H,D,T]
__device__ float g_sc [(long)Bsz * NH * Tseq * Tseq]; // scores / attn (in-place softmax)
__device__ float g_ctx[NTOK * EMB];                 // [B,T,E]
__device__ float g_x2 [NTOK * EMB];                 // residual after attention
__device__ float g_ffn[NTOK * FFND];                // gelu(h @ W1^T)

// ---------------------------------------------------------------------------
// Block reduction helpers (blockDim.x == 256)
// ---------------------------------------------------------------------------
__device__ __forceinline__ float blk_sum(float v, float* s) {
    int t = threadIdx.x;
    #pragma unroll
    for (int o = 16; o; o >>= 1) v += __shfl_xor_sync(0xffffffffu, v, o);
    if ((t & 31) == 0) s[t >> 5] = v;
    __syncthreads();
    if (t < 32) {
        float w = (t < 8) ? s[t] : 0.0f;
        #pragma unroll
        for (int o = 4; o; o >>= 1) w += __shfl_xor_sync(0xffffffffu, w, o);
        if (t == 0) s[0] = w;
    }
    __syncthreads();
    float r = s[0];
    __syncthreads();
    return r;
}

__device__ __forceinline__ float blk_max(float v, float* s) {
    int t = threadIdx.x;
    #pragma unroll
    for (int o = 16; o; o >>= 1) v = fmaxf(v, __shfl_xor_sync(0xffffffffu, v, o));
    if ((t & 31) == 0) s[t >> 5] = v;
    __syncthreads();
    if (t < 32) {
        float w = (t < 8) ? s[t] : -INFINITY;
        #pragma unroll
        for (int o = 4; o; o >>= 1) w = fmaxf(w, __shfl_xor_sync(0xffffffffu, w, o));
        if (t == 0) s[0] = w;
    }
    __syncthreads();
    float r = s[0];
    __syncthreads();
    return r;
}

// ---------------------------------------------------------------------------
// LayerNorm: one block per row of 768
// ---------------------------------------------------------------------------
__global__ void layernorm_k(const float* __restrict__ x, float* __restrict__ o,
                            const float* __restrict__ sc, const float* __restrict__ sh) {
    __shared__ float red[32];
    long row = blockIdx.x;
    const float* p = x + row * EMB;
    float* q = o + row * EMB;
    int t = threadIdx.x;
    float a0 = p[t], a1 = p[t + 256], a2 = p[t + 512];
    float mean = blk_sum(a0 + a1 + a2, red) * (1.0f / EMB);
    float d0 = a0 - mean, d1 = a1 - mean, d2 = a2 - mean;
    float var = blk_sum(d0 * d0 + d1 * d1 + d2 * d2, red) * (1.0f / EMB);
    float rstd = rsqrtf(var + 1e-5f);
    q[t      ] = d0 * rstd * sc[t      ] + sh[t      ];
    q[t + 256] = d1 * rstd * sc[t + 256] + sh[t + 256];
    q[t + 512] = d2 * rstd * sc[t + 512] + sh[t + 512];
}

// ---------------------------------------------------------------------------
// Row softmax over 1024 columns (in place). One block per row, 256 threads.
// ---------------------------------------------------------------------------
__global__ void softmax_k(float* __restrict__ S) {
    __shared__ float red[32];
    long row = blockIdx.x;
    float4* p = (float4*)(S + row * (long)Tseq);
    int t = threadIdx.x;
    float4 v = p[t];
    float m = blk_max(fmaxf(fmaxf(v.x, v.y), fmaxf(v.z, v.w)), red);
    float e0 = __expf(v.x - m), e1 = __expf(v.y - m);
    float e2 = __expf(v.z - m), e3 = __expf(v.w - m);
    float z = blk_sum(e0 + e1 + e2 + e3, red);
    float inv = 1.0f / z;
    p[t] = make_float4(e0 * inv, e1 * inv, e2 * inv, e3 * inv);
}

// ---------------------------------------------------------------------------
// Generic NT GEMM:  C[m,n] = sum_k A[m,k] * B[n,k]   (both row-major, K-contig)
// Tiling: BM=BN=64, BK=32, 16x16 threads, 4x4 microtile.
// Epilogues select output layout / fusion.
// ---------------------------------------------------------------------------
#define EPI_PLAIN  0
#define EPI_SCORES 1   // *0.125, causal mask, tile-level skip
#define EPI_QK     2   // scatter [tok,E] -> [B,H,T,D]
#define EPI_VT     3   // scatter [tok,E] -> [B,H,D,T]
#define EPI_CTX    4   // scatter per-(b,h) [T,D] -> [B,T,E]
#define EPI_RES    5   // + residual R (same layout as C)
#define EPI_GELU   6   // gelu(acc)

#define BM 64
#define BN 64
#define BK 32

__global__ void gemm_nt(const float* __restrict__ A, const float* __restrict__ Bm,
                        const float* __restrict__ R, float* __restrict__ C,
                        int M, int N, int K,
                        long sA, long sB, long sC, int epi) {
    int z = blockIdx.z;
    const float* Ab = A + (long)z * sA;
    const float* Bb = Bm + (long)z * sB;

    int bx = blockIdx.x, by = blockIdx.y;
    int row0 = by * BM, col0 = bx * BN;
    int tx = threadIdx.x, ty = threadIdx.y;
    int tid = ty * 16 + tx;

    if (epi == EPI_SCORES && bx > by) {
        // tile entirely above the causal diagonal: write mask value only
        float* Cp = C + (long)z * sC;
        for (int i = tid; i < BM * BN; i += 256) {
            int r = i >> 6, c = i & 63;
            Cp[(long)(row0 + r) * N + col0 + c] = -1e30f;
        }
        return;
    }

    __shared__ float As[BK][BM + 4];
    __shared__ float Bs[BK][BN + 4];

    float acc[4][4] = {};

    for (int k0 = 0; k0 < K; k0 += BK) {
        #pragma unroll
        for (int i = 0; i < 2; i++) {
            int idx = tid + i * 256;          // 512 float4 slots
            int r = idx >> 3;                 // 8 float4 per 32-wide row
            int cc = (idx & 7) * 4;
            float4 v = *(const float4*)&Ab[(long)(row0 + r) * K + k0 + cc];
            As[cc + 0][r] = v.x; As[cc + 1][r] = v.y;
            As[cc + 2][r] = v.z; As[cc + 3][r] = v.w;
        }
        #pragma unroll
        for (int i = 0; i < 2; i++) {
            int idx = tid + i * 256;
            int r = idx >> 3;
            int cc = (idx & 7) * 4;
            float4 v = *(const float4*)&Bb[(long)(col0 + r) * K + k0 + cc];
            Bs[cc + 0][r] = v.x; Bs[cc + 1][r] = v.y;
            Bs[cc + 2][r] = v.z; Bs[cc + 3][r] = v.w;
        }
        __syncthreads();
        #pragma unroll
        for (int k = 0; k < BK; k++) {
            float4 a = *(const float4*)&As[k][ty * 4];
            float4 b = *(const float4*)&Bs[k][tx * 4];
            acc[0][0] += a.x * b.x; acc[0][1] += a.x * b.y; acc[0][2] += a.x * b.z; acc[0][3] += a.x * b.w;
            acc[1][0] += a.y * b.x; acc[1][1] += a.y * b.y; acc[1][2] += a.y * b.z; acc[1][3] += a.y * b.w;
            acc[2][0] += a.z * b.x; acc[2][1] += a.z * b.y; acc[2][2] += a.z * b.z; acc[2][3] += a.z * b.w;
            acc[3][0] += a.w * b.x; acc[3][1] += a.w * b.y; acc[3][2] += a.w * b.z; acc[3][3] += a.w * b.w;
        }
        __syncthreads();
    }

    int r0 = row0 + ty * 4;
    int c0 = col0 + tx * 4;

    switch (epi) {
    case EPI_PLAIN: {
        float* Cp = C + (long)z * sC;
        #pragma unroll
        for (int i = 0; i < 4; i++)
            #pragma unroll
            for (int j = 0; j < 4; j++)
                Cp[(long)(r0 + i) * N + c0 + j] = acc[i][j];
        break; }
    case EPI_SCORES: {
        float* Cp = C + (long)z * sC;
        #pragma unroll
        for (int i = 0; i < 4; i++)
            #pragma unroll
            for (int j = 0; j < 4; j++) {
                float v = acc[i][j] * 0.125f;               // 1/sqrt(64)
                if (c0 + j > r0 + i) v = -1e30f;            // causal mask
                Cp[(long)(r0 + i) * N + c0 + j] = v;
            }
        break; }
    case EPI_QK: {
        #pragma unroll
        for (int i = 0; i < 4; i++) {
            int gm = r0 + i;
            int b = gm >> 10, t = gm & 1023;
            #pragma unroll
            for (int j = 0; j < 4; j++) {
                int gn = c0 + j;
                int h = gn >> 6, d = gn & 63;
                C[(((long)(b * NH + h) << 10) + t) * HD + d] = acc[i][j];
            }
        }
        break; }
    case EPI_VT: {
        #pragma unroll
        for (int i = 0; i < 4; i++) {
            int gm = r0 + i;
            int b = gm >> 10, t = gm & 1023;
            #pragma unroll
            for (int j = 0; j < 4; j++) {
                int gn = c0 + j;
                int h = gn >> 6, d = gn & 63;
                C[((long)(b * NH + h) * HD + d) * Tseq + t] = acc[i][j];
            }
        }
        break; }
    case EPI_CTX: {
        int b = z / NH, h = z % NH;
        #pragma unroll
        for (int i = 0; i < 4; i++)
            #pragma unroll
            for (int j = 0; j < 4; j++)
                C[((long)(b * Tseq + r0 + i)) * EMB + h * HD + c0 + j] = acc[i][j];
        break; }
    case EPI_RES: {
        #pragma unroll
        for (int i = 0; i < 4; i++)
            #pragma unroll
            for (int j = 0; j < 4; j++) {
                long o = (long)(r0 + i) * N + c0 + j;
                C[o] = acc[i][j] + R[o];
            }
        break; }
    case EPI_GELU: {
        const float cst = 0.7978845608028654f;
        #pragma unroll
        for (int i = 0; i < 4; i++)
            #pragma unroll
            for (int j = 0; j < 4; j++) {
                float u = acc[i][j];
                float g = 0.5f * u * (1.0f + tanhf(cst * (u + 0.044715f * u * u * u)));
                C[(long)(r0 + i) * N + c0 + j] = g;
            }
        break; }
    }
}

// ---------------------------------------------------------------------------
// Launch
// ---------------------------------------------------------------------------
extern "C" void kernel_launch(void* const* d_in, const int* in_sizes, int n_in,
                              void* d_out, int out_size) {
    const float* x    = (const float*)d_in[0];
    const float* wq   = (const float*)d_in[1];
    const float* wk   = (const float*)d_in[2];
    const float* wv   = (const float*)d_in[3];
    const float* wo   = (const float*)d_in[4];
    const float* w1   = (const float*)d_in[5];
    const float* w2   = (const float*)d_in[6];
    const float* ln1s = (const float*)d_in[7];
    const float* ln1b = (const float*)d_in[8];
    const float* ln2s = (const float*)d_in[9];
    const float* ln2b = (const float*)d_in[10];
    float* out = (float*)d_out;

    float *h, *q, *k, *vt, *sc, *ctx, *x2, *ffn;
    cudaGetSymbolAddress((void**)&h,   g_h);
    cudaGetSymbolAddress((void**)&q,   g_q);
    cudaGetSymbolAddress((void**)&k,   g_k);
    cudaGetSymbolAddress((void**)&vt,  g_vt);
    cudaGetSymbolAddress((void**)&sc,  g_sc);
    cudaGetSymbolAddress((void**)&ctx, g_ctx);
    cudaGetSymbolAddress((void**)&x2,  g_x2);
    cudaGetSymbolAddress((void**)&ffn, g_ffn);

    dim3 tb(16, 16);

    // 1) LN1
    layernorm_k<<<NTOK, 256>>>(x, h, ln1s, ln1b);

    // 2-4) QKV projections (fused reshape)
    gemm_nt<<<dim3(EMB / BN, NTOK / BM, 1), tb>>>(h, wq, nullptr, q,  NTOK, EMB, EMB, 0, 0, 0, EPI_QK);
    gemm_nt<<<dim3(EMB / BN, NTOK / BM, 1), tb>>>(h, wk, nullptr, k,  NTOK, EMB, EMB, 0, 0, 0, EPI_QK);
    gemm_nt<<<dim3(EMB / BN, NTOK / BM, 1), tb>>>(h, wv, nullptr, vt, NTOK, EMB, EMB, 0, 0, 0, EPI_VT);

    // 5) scores = QK^T/8 with causal mask; batched over B*H
    gemm_nt<<<dim3(Tseq / BN, Tseq / BM, Bsz * NH), tb>>>(
        q, k, nullptr, sc, Tseq, Tseq, HD,
        (long)Tseq * HD, (long)Tseq * HD, (long)Tseq * Tseq, EPI_SCORES);

    // 6) softmax rows
    softmax_k<<<Bsz * NH * Tseq, 256>>>(sc);

    // 7) ctx = attn @ V; batched, scatter to [B,T,E]
    gemm_nt<<<dim3(HD / BN, Tseq / BM, Bsz * NH), tb>>>(
        sc, vt, nullptr, ctx, Tseq, HD, Tseq,
        (long)Tseq * Tseq, (long)HD * Tseq, 0, EPI_CTX);

    // 8) x2 = x + ctx @ Wo^T
    gemm_nt<<<dim3(EMB / BN, NTOK / BM, 1), tb>>>(ctx, wo, x, x2, NTOK, EMB, EMB, 0, 0, 0, EPI_RES);

    // 9) LN2
    layernorm_k<<<NTOK, 256>>>(x2, h, ln2s, ln2b);

    // 10) ffn = gelu(h @ W1^T)
    gemm_nt<<<dim3(FFND / BN, NTOK / BM, 1), tb>>>(h, w1, nullptr, ffn, NTOK, FFND, EMB, 0, 0, 0, EPI_GELU);

    // 11) out = x2 + ffn @ W2^T
    gemm_nt<<<dim3(EMB / BN, NTOK / BM, 1), tb>>>(ffn, w2, x2, out, NTOK, EMB, FFND, 0, 0, 0, EPI_RES);
}

// round 3
// speedup vs baseline: 2.9102x; 2.9077x over previous
#include <cuda_runtime.h>
#include <cuda_bf16.h>
#include <math.h>
#include <stdint.h>

// ---------------------------------------------------------------------------
// Problem constants
// ---------------------------------------------------------------------------
#define Bsz   8
#define Tseq  1024
#define EMB   768
#define NH    12
#define HD    64
#define NTOK  (Bsz * Tseq)          // 8192
#define FFND  (4 * EMB)             // 3072

// ---------------------------------------------------------------------------
// Scratch (device globals — allocation-free)
// ---------------------------------------------------------------------------
__device__ float g_h  [NTOK * EMB];                   // LN output
__device__ float g_q  [NTOK * EMB];                   // [B,H,T,D]
__device__ float g_k  [NTOK * EMB];                   // [B,H,T,D]
__device__ float g_vt [NTOK * EMB];                   // [B,H,D,T]
__device__ float g_sc [(long)Bsz * NH * Tseq * Tseq]; // scores / attn
__device__ float g_ctx[NTOK * EMB];                   // [B,T,E]
__device__ float g_x2 [NTOK * EMB];                   // residual after attention
__device__ float g_ffn[NTOK * FFND];                  // gelu(h @ W1^T)

// ---------------------------------------------------------------------------
// Block reduction helpers (blockDim.x == 256)
// ---------------------------------------------------------------------------
__device__ __forceinline__ float blk_sum(float v, float* s) {
    int t = threadIdx.x;
    #pragma unroll
    for (int o = 16; o; o >>= 1) v += __shfl_xor_sync(0xffffffffu, v, o);
    if ((t & 31) == 0) s[t >> 5] = v;
    __syncthreads();
    if (t < 32) {
        float w = (t < 8) ? s[t] : 0.0f;
        #pragma unroll
        for (int o = 4; o; o >>= 1) w += __shfl_xor_sync(0xffffffffu, w, o);
        if (t == 0) s[0] = w;
    }
    __syncthreads();
    float r = s[0];
    __syncthreads();
    return r;
}

__device__ __forceinline__ float blk_max(float v, float* s) {
    int t = threadIdx.x;
    #pragma unroll
    for (int o = 16; o; o >>= 1) v = fmaxf(v, __shfl_xor_sync(0xffffffffu, v, o));
    if ((t & 31) == 0) s[t >> 5] = v;
    __syncthreads();
    if (t < 32) {
        float w = (t < 8) ? s[t] : -INFINITY;
        #pragma unroll
        for (int o = 4; o; o >>= 1) w = fmaxf(w, __shfl_xor_sync(0xffffffffu, w, o));
        if (t == 0) s[0] = w;
    }
    __syncthreads();
    float r = s[0];
    __syncthreads();
    return r;
}

// ---------------------------------------------------------------------------
// LayerNorm: one block per row of 768
// ---------------------------------------------------------------------------
__global__ void layernorm_k(const float* __restrict__ x, float* __restrict__ o,
                            const float* __restrict__ sc, const float* __restrict__ sh) {
    __shared__ float red[32];
    long row = blockIdx.x;
    const float* p = x + row * EMB;
    float* q = o + row * EMB;
    int t = threadIdx.x;
    float a0 = p[t], a1 = p[t + 256], a2 = p[t + 512];
    float mean = blk_sum(a0 + a1 + a2, red) * (1.0f / EMB);
    float d0 = a0 - mean, d1 = a1 - mean, d2 = a2 - mean;
    float var = blk_sum(d0 * d0 + d1 * d1 + d2 * d2, red) * (1.0f / EMB);
    float rstd = rsqrtf(var + 1e-5f);
    q[t      ] = d0 * rstd * sc[t      ] + sh[t      ];
    q[t + 256] = d1 * rstd * sc[t + 256] + sh[t + 256];
    q[t + 512] = d2 * rstd * sc[t + 512] + sh[t + 512];
}

// ---------------------------------------------------------------------------
// Row softmax over 1024 columns (in place). One block per row, 256 threads.
// ---------------------------------------------------------------------------
__global__ void softmax_k(float* __restrict__ S) {
    __shared__ float red[32];
    long row = blockIdx.x;
    float4* p = (float4*)(S + row * (long)Tseq);
    int t = threadIdx.x;
    float4 v = p[t];
    float m = blk_max(fmaxf(fmaxf(v.x, v.y), fmaxf(v.z, v.w)), red);
    float e0 = __expf(v.x - m), e1 = __expf(v.y - m);
    float e2 = __expf(v.z - m), e3 = __expf(v.w - m);
    float z = blk_sum(e0 + e1 + e2 + e3, red);
    float inv = 1.0f / z;
    p[t] = make_float4(e0 * inv, e1 * inv, e2 * inv, e3 * inv);
}

// ---------------------------------------------------------------------------
// Tensor-core NT GEMM (tf32 mma.sync, m16n8k8):
//   C[m,n] = sum_k A[m,k]*B[n,k]  (both row-major, K contiguous)
// CTA tile BM x BN x 32, 256 threads = 8 warps arranged WM x WN.
// ---------------------------------------------------------------------------
#define EPI_SCORES 1
#define EPI_QK     2
#define EPI_VT     3
#define EPI_CTX    4
#define EPI_RES    5
#define EPI_GELU   6

__device__ __forceinline__ float to_tf32(float x) {
    uint32_t r;
    asm("cvt.rna.tf32.f32 %0, %1;" : "=r"(r) : "f"(x));
    return __uint_as_float(r);
}

__device__ __forceinline__ void mma_tf32(float* d, const uint32_t* a, const uint32_t* b) {
    asm volatile(
        "mma.sync.aligned.m16n8k8.row.col.f32.tf32.tf32.f32 "
        "{%0,%1,%2,%3}, {%4,%5,%6,%7}, {%8,%9}, {%0,%1,%2,%3};"
        : "+f"(d[0]), "+f"(d[1]), "+f"(d[2]), "+f"(d[3])
        : "r"(a[0]), "r"(a[1]), "r"(a[2]), "r"(a[3]), "r"(b[0]), "r"(b[1]));
}

template<int BM, int BN, int WM, int WN, int EPI>
__global__ void gemm_tc(const float* __restrict__ A, const float* __restrict__ Bm,
                        const float* __restrict__ R, float* __restrict__ C,
                        int M, int N, int K, long sA, long sB, long sC) {
    constexpr int BK  = 32;
    constexpr int WTM = BM / WM;         // warp tile rows
    constexpr int WTN = BN / WN;         // warp tile cols
    constexpr int MF  = WTM / 16;        // m fragments per warp
    constexpr int NF  = WTN / 8;         // n fragments per warp
    constexpr int PAD = 4;               // smem stride BK+4=36 -> conflict-free frags

    const int tid  = threadIdx.x;
    const int z    = blockIdx.z;
    const int row0 = blockIdx.y * BM;
    const int col0 = blockIdx.x * BN;

    if (EPI == EPI_SCORES && blockIdx.x > blockIdx.y) {
        // fully-masked causal tile
        float* Cp = C + (long)z * sC;
        const float4 mval = make_float4(-1e30f, -1e30f, -1e30f, -1e30f);
        #pragma unroll
        for (int i = 0; i < BM * BN / (256 * 4); i++) {
            int idx = tid + i * 256;
            int r = idx / (BN / 4), c = (idx % (BN / 4)) * 4;
            *(float4*)&Cp[(long)(row0 + r) * N + col0 + c] = mval;
        }
        return;
    }

    __shared__ float As[BM][BK + PAD];
    __shared__ float Bs[BN][BK + PAD];

    const int lane = tid & 31;
    const int w    = tid >> 5;
    const int g    = lane >> 2;          // group id 0..7
    const int tig  = lane & 3;           // thread-in-group 0..3
    const int wm   = w % WM;
    const int wn   = w / WM;
    const int rw   = wm * WTM;           // warp row offset in tile
    const int cw   = wn * WTN;           // warp col offset in tile

    const float* Ab = A + (long)z * sA;
    const float* Bb = Bm + (long)z * sB;

    float acc[MF][NF][4] = {};

    constexpr int A_ITERS = BM * BK / (256 * 4);
    constexpr int B_ITERS = BN * BK / (256 * 4);

    for (int k0 = 0; k0 < K; k0 += BK) {
        #pragma unroll
        for (int i = 0; i < A_ITERS; i++) {
            int idx = tid + i * 256;
            int r = idx >> 3, c = (idx & 7) * 4;
            float4 v = *(const float4*)&Ab[(long)(row0 + r) * K + k0 + c];
            v.x = to_tf32(v.x); v.y = to_tf32(v.y);
            v.z = to_tf32(v.z); v.w = to_tf32(v.w);
            *(float4*)&As[r][c] = v;
        }
        #pragma unroll
        for (int i = 0; i < B_ITERS; i++) {
            int idx = tid + i * 256;
            int r = idx >> 3, c = (idx & 7) * 4;
            float4 v = *(const float4*)&Bb[(long)(col0 + r) * K + k0 + c];
            v.x = to_tf32(v.x); v.y = to_tf32(v.y);
            v.z = to_tf32(v.z); v.w = to_tf32(v.w);
            *(float4*)&Bs[r][c] = v;
        }
        __syncthreads();

        #pragma unroll
        for (int kk = 0; kk < BK; kk += 8) {
            uint32_t afr[MF][4], bfr[NF][2];
            #pragma unroll
            for (int mi = 0; mi < MF; mi++) {
                int r = rw + mi * 16 + g;
                afr[mi][0] = __float_as_uint(As[r    ][kk + tig    ]);
                afr[mi][1] = __float_as_uint(As[r + 8][kk + tig    ]);
                afr[mi][2] = __float_as_uint(As[r    ][kk + tig + 4]);
                afr[mi][3] = __float_as_uint(As[r + 8][kk + tig + 4]);
            }
            #pragma unroll
            for (int ni = 0; ni < NF; ni++) {
                int c = cw + ni * 8 + g;
                bfr[ni][0] = __float_as_uint(Bs[c][kk + tig    ]);
                bfr[ni][1] = __float_as_uint(Bs[c][kk + tig + 4]);
            }
            #pragma unroll
            for (int mi = 0; mi < MF; mi++)
                #pragma unroll
                for (int ni = 0; ni < NF; ni++)
                    mma_tf32(acc[mi][ni], afr[mi], bfr[ni]);
        }
        __syncthreads();
    }

    // ---------------- epilogue ----------------
    // fragment element (mi,ni): rows row0+rw+mi*16+g (+8), cols col0+cw+ni*8+2*tig (+1)
    #pragma unroll
    for (int mi = 0; mi < MF; mi++) {
        #pragma unroll
        for (int ni = 0; ni < NF; ni++) {
            int r_ = row0 + rw + mi * 16 + g;
            int c_ = col0 + cw + ni * 8 + tig * 2;
            float* a4 = acc[mi][ni];
            #pragma unroll
            for (int half = 0; half < 2; half++) {
                int rr = r_ + half * 8;
                float v0 = a4[half * 2 + 0];
                float v1 = a4[half * 2 + 1];

                if (EPI == EPI_SCORES) {
                    float* Cp = C + (long)z * sC;
                    v0 *= 0.125f; v1 *= 0.125f;
                    if (c_     > rr) v0 = -1e30f;
                    if (c_ + 1 > rr) v1 = -1e30f;
                    *(float2*)&Cp[(long)rr * N + c_] = make_float2(v0, v1);
                } else if (EPI == EPI_QK) {
                    int b = rr >> 10, t = rr & 1023;
                    int h = c_ >> 6,  d = c_ & 63;   // c_, c_+1 share h (2 | 64)
                    long o = (((long)(b * NH + h) << 10) + t) * HD + d;
                    *(float2*)&C[o] = make_float2(v0, v1);
                } else if (EPI == EPI_VT) {
                    int b = rr >> 10, t = rr & 1023;
                    int h = c_ >> 6,  d = c_ & 63;
                    C[((long)(b * NH + h) * HD + d    ) * Tseq + t] = v0;
                    C[((long)(b * NH + h) * HD + d + 1) * Tseq + t] = v1;
                } else if (EPI == EPI_CTX) {
                    int b = z / NH, h = z % NH;
                    long o = ((long)(b * Tseq + rr)) * EMB + h * HD + c_;
                    *(float2*)&C[o] = make_float2(v0, v1);
                } else if (EPI == EPI_RES) {
                    long o = (long)rr * N + c_;
                    float2 rv = *(const float2*)&R[o];
                    *(float2*)&C[o] = make_float2(v0 + rv.x, v1 + rv.y);
                } else if (EPI == EPI_GELU) {
                    const float cst = 0.7978845608028654f;
                    float gl0 = 0.5f * v0 * (1.0f + tanhf(cst * (v0 + 0.044715f * v0 * v0 * v0)));
                    float gl1 = 0.5f * v1 * (1.0f + tanhf(cst * (v1 + 0.044715f * v1 * v1 * v1)));
                    *(float2*)&C[(long)rr * N + c_] = make_float2(gl0, gl1);
                }
            }
        }
    }
}

// ---------------------------------------------------------------------------
// Launch
// ---------------------------------------------------------------------------
extern "C" void kernel_launch(void* const* d_in, const int* in_sizes, int n_in,
                              void* d_out, int out_size) {
    const float* x    = (const float*)d_in[0];
    const float* wq   = (const float*)d_in[1];
    const float* wk   = (const float*)d_in[2];
    const float* wv   = (const float*)d_in[3];
    const float* wo   = (const float*)d_in[4];
    const float* w1   = (const float*)d_in[5];
    const float* w2   = (const float*)d_in[6];
    const float* ln1s = (const float*)d_in[7];
    const float* ln1b = (const float*)d_in[8];
    const float* ln2s = (const float*)d_in[9];
    const float* ln2b = (const float*)d_in[10];
    float* out = (float*)d_out;

    float *h, *q, *k, *vt, *sc, *ctx, *x2, *ffn;
    cudaGetSymbolAddress((void**)&h,   g_h);
    cudaGetSymbolAddress((void**)&q,   g_q);
    cudaGetSymbolAddress((void**)&k,   g_k);
    cudaGetSymbolAddress((void**)&vt,  g_vt);
    cudaGetSymbolAddress((void**)&sc,  g_sc);
    cudaGetSymbolAddress((void**)&ctx, g_ctx);
    cudaGetSymbolAddress((void**)&x2,  g_x2);
    cudaGetSymbolAddress((void**)&ffn, g_ffn);

    // 1) LN1
    layernorm_k<<<NTOK, 256>>>(x, h, ln1s, ln1b);

    // 2-4) QKV projections (fused reshape) : M=8192, N=768, K=768
    gemm_tc<128,128,2,4,EPI_QK><<<dim3(EMB/128, NTOK/128, 1), 256>>>(
        h, wq, nullptr, q, NTOK, EMB, EMB, 0, 0, 0);
    gemm_tc<128,128,2,4,EPI_QK><<<dim3(EMB/128, NTOK/128, 1), 256>>>(
        h, wk, nullptr, k, NTOK, EMB, EMB, 0, 0, 0);
    gemm_tc<128,128,2,4,EPI_VT><<<dim3(EMB/128, NTOK/128, 1), 256>>>(
        h, wv, nullptr, vt, NTOK, EMB, EMB, 0, 0, 0);

    // 5) scores = QK^T/8 + causal mask; batched over B*H : M=N=1024, K=64
    gemm_tc<128,128,2,4,EPI_SCORES><<<dim3(Tseq/128, Tseq/128, Bsz*NH), 256>>>(
        q, k, nullptr, sc, Tseq, Tseq, HD,
        (long)Tseq * HD, (long)Tseq * HD, (long)Tseq * Tseq);

    // 6) softmax rows
    softmax_k<<<Bsz * NH * Tseq, 256>>>(sc);

    // 7) ctx = attn @ V : M=1024, N=64, K=1024, batched; scatter to [B,T,E]
    gemm_tc<128,64,4,2,EPI_CTX><<<dim3(1, Tseq/128, Bsz*NH), 256>>>(
        sc, vt, nullptr, ctx, Tseq, HD, Tseq,
        (long)Tseq * Tseq, (long)HD * Tseq, 0);

    // 8) x2 = x + ctx @ Wo^T : M=8192, N=768, K=768
    gemm_tc<128,128,2,4,EPI_RES><<<dim3(EMB/128, NTOK/128, 1), 256>>>(
        ctx, wo, x, x2, NTOK, EMB, EMB, 0, 0, 0);

    // 9) LN2
    layernorm_k<<<NTOK, 256>>>(x2, h, ln2s, ln2b);

    // 10) ffn = gelu(h @ W1^T) : M=8192, N=3072, K=768
    gemm_tc<128,128,2,4,EPI_GELU><<<dim3(FFND/128, NTOK/128, 1), 256>>>(
        h, w1, nullptr, ffn, NTOK, FFND, EMB, 0, 0, 0);

    // 11) out = x2 + ffn @ W2^T : M=8192, N=768, K=3072
    gemm_tc<128,128,2,4,EPI_RES><<<dim3(EMB/128, NTOK/128, 1), 256>>>(
        ffn, w2, x2, out, NTOK, EMB, FFND, 0, 0, 0);
}

// round 4
// speedup vs baseline: 3.0733x; 1.0561x over previous
#include <cuda_runtime.h>
#include <cuda_bf16.h>
#include <math.h>
#include <stdint.h>

// ---------------------------------------------------------------------------
// Problem constants
// ---------------------------------------------------------------------------
#define Bsz   8
#define Tseq  1024
#define EMB   768
#define NH    12
#define HD    64
#define NTOK  (Bsz * Tseq)          // 8192
#define FFND  (4 * EMB)             // 3072

// ---------------------------------------------------------------------------
// Scratch (device globals — allocation-free)
// ---------------------------------------------------------------------------
__device__ float g_h  [NTOK * EMB];                   // LN output
__device__ float g_q  [NTOK * EMB];                   // [B,H,T,D]
__device__ float g_k  [NTOK * EMB];                   // [B,H,T,D]
__device__ float g_v  [NTOK * EMB];                   // [B,H,T,D]
__device__ float g_sc [(long)Bsz * NH * Tseq * Tseq]; // scores / attn
__device__ float g_ctx[NTOK * EMB];                   // [B,T,E]
__device__ float g_x2 [NTOK * EMB];                   // residual after attention
__device__ float g_ffn[NTOK * FFND];                  // gelu(h @ W1^T)

// ---------------------------------------------------------------------------
// cp.async helpers
// ---------------------------------------------------------------------------
__device__ __forceinline__ void cp16(void* dst, const void* src) {
    uint32_t d = (uint32_t)__cvta_generic_to_shared(dst);
    asm volatile("cp.async.ca.shared.global [%0], [%1], 16;" :: "r"(d), "l"(src));
}
__device__ __forceinline__ void cp_commit() {
    asm volatile("cp.async.commit_group;" ::: "memory");
}
template<int N>
__device__ __forceinline__ void cp_wait() {
    asm volatile("cp.async.wait_group %0;" :: "n"(N) : "memory");
}

// ---------------------------------------------------------------------------
// Block reduction helpers (blockDim.x == 256)
// ---------------------------------------------------------------------------
__device__ __forceinline__ float blk_sum(float v, float* s) {
    int t = threadIdx.x;
    #pragma unroll
    for (int o = 16; o; o >>= 1) v += __shfl_xor_sync(0xffffffffu, v, o);
    if ((t & 31) == 0) s[t >> 5] = v;
    __syncthreads();
    if (t < 32) {
        float w = (t < 8) ? s[t] : 0.0f;
        #pragma unroll
        for (int o = 4; o; o >>= 1) w += __shfl_xor_sync(0xffffffffu, w, o);
        if (t == 0) s[0] = w;
    }
    __syncthreads();
    float r = s[0];
    __syncthreads();
    return r;
}

__device__ __forceinline__ float blk_max(float v, float* s) {
    int t = threadIdx.x;
    #pragma unroll
    for (int o = 16; o; o >>= 1) v = fmaxf(v, __shfl_xor_sync(0xffffffffu, v, o));
    if ((t & 31) == 0) s[t >> 5] = v;
    __syncthreads();
    if (t < 32) {
        float w = (t < 8) ? s[t] : -INFINITY;
        #pragma unroll
        for (int o = 4; o; o >>= 1) w = fmaxf(w, __shfl_xor_sync(0xffffffffu, w, o));
        if (t == 0) s[0] = w;
    }
    __syncthreads();
    float r = s[0];
    __syncthreads();
    return r;
}

// ---------------------------------------------------------------------------
// LayerNorm: one block per row of 768
// ---------------------------------------------------------------------------
__global__ void layernorm_k(const float* __restrict__ x, float* __restrict__ o,
                            const float* __restrict__ sc, const float* __restrict__ sh) {
    __shared__ float red[32];
    long row = blockIdx.x;
    const float* p = x + row * EMB;
    float* q = o + row * EMB;
    int t = threadIdx.x;
    float a0 = p[t], a1 = p[t + 256], a2 = p[t + 512];
    float mean = blk_sum(a0 + a1 + a2, red) * (1.0f / EMB);
    float d0 = a0 - mean, d1 = a1 - mean, d2 = a2 - mean;
    float var = blk_sum(d0 * d0 + d1 * d1 + d2 * d2, red) * (1.0f / EMB);
    float rstd = rsqrtf(var + 1e-5f);
    q[t      ] = d0 * rstd * sc[t      ] + sh[t      ];
    q[t + 256] = d1 * rstd * sc[t + 256] + sh[t + 256];
    q[t + 512] = d2 * rstd * sc[t + 512] + sh[t + 512];
}

// ---------------------------------------------------------------------------
// Causal softmax over 1024 columns (in place). One block per row, 256 threads.
// Masks by position; never reads fully-masked quads (those tiles were never
// written by the scores GEMM); writes zeros there so the ctx GEMM can read.
// ---------------------------------------------------------------------------
__global__ void softmax_k(float* __restrict__ S) {
    __shared__ float red[32];
    long row = blockIdx.x;
    int rowpos = (int)(row & (Tseq - 1));
    float4* p = (float4*)(S + row * (long)Tseq);
    int t = threadIdx.x;
    int c = 4 * t;
    float4 v = make_float4(-INFINITY, -INFINITY, -INFINITY, -INFINITY);
    bool live = (c <= rowpos);
    if (live) {
        v = p[t];
        if (c + 1 > rowpos) v.y = -INFINITY;
        if (c + 2 > rowpos) v.z = -INFINITY;
        if (c + 3 > rowpos) v.w = -INFINITY;
    }
    float m = blk_max(fmaxf(fmaxf(v.x, v.y), fmaxf(v.z, v.w)), red);
    float e0 = __expf(v.x - m), e1 = __expf(v.y - m);
    float e2 = __expf(v.z - m), e3 = __expf(v.w - m);
    float z = blk_sum(e0 + e1 + e2 + e3, red);
    float inv = 1.0f / z;
    p[t] = make_float4(e0 * inv, e1 * inv, e2 * inv, e3 * inv);
}

// ---------------------------------------------------------------------------
// Tensor-core GEMM (tf32 mma.sync m16n8k8), 2-stage cp.async pipeline.
//   TRB=false:  C[m,n] = sum_k A[m,k] * B[n,k]   (NT; both K-contiguous)
//   TRB=true :  C[m,n] = sum_k A[m,k] * B[k,n]   (NN; B is [K,N] row-major)
// CTA tile BM x BN x 32, 256 threads = 8 warps (WM x WN).
// ---------------------------------------------------------------------------
#define EPI_SCORES 1
#define EPI_QK     2
#define EPI_CTX    4
#define EPI_RES    5
#define EPI_GELU   6

__device__ __forceinline__ uint32_t tf32_of(float x) {
    uint32_t r;
    asm("cvt.rna.tf32.f32 %0, %1;" : "=r"(r) : "f"(x));
    return r;
}

__device__ __forceinline__ void mma_tf32(float* d, const uint32_t* a, const uint32_t* b) {
    asm volatile(
        "mma.sync.aligned.m16n8k8.row.col.f32.tf32.tf32.f32 "
        "{%0,%1,%2,%3}, {%4,%5,%6,%7}, {%8,%9}, {%0,%1,%2,%3};"
        : "+f"(d[0]), "+f"(d[1]), "+f"(d[2]), "+f"(d[3])
        : "r"(a[0]), "r"(a[1]), "r"(a[2]), "r"(a[3]), "r"(b[0]), "r"(b[1]));
}

template<int BM, int BN, int WM, int WN, int EPI, bool TRB>
__global__ void gemm_tc(const float* __restrict__ A, const float* __restrict__ Bm,
                        const float* __restrict__ R, float* __restrict__ C,
                        int M, int N, int K, long sA, long sB, long sC) {
    constexpr int BK  = 32;
    constexpr int PAD = 4;
    constexpr int LD  = BK + PAD;        // 36 floats -> 144B rows (16B aligned)
    constexpr int WTM = BM / WM;
    constexpr int WTN = BN / WN;
    constexpr int MF  = WTM / 16;
    constexpr int NF  = WTN / 8;

    const int tid  = threadIdx.x;
    const int z    = blockIdx.z;
    const int row0 = blockIdx.y * BM;
    const int col0 = blockIdx.x * BN;

    if (EPI == EPI_SCORES && blockIdx.x > blockIdx.y) return;  // masked tile: skip

    extern __shared__ float smem[];
    float* As = smem;                    // [2][BM][LD]
    float* Bs = smem + 2 * BM * LD;      // [2][BN][LD]

    const float* Ab = A + (long)z * sA;
    const float* Bb = Bm + (long)z * sB;

    constexpr int A_ITERS = BM * BK / (256 * 4);

    auto load_tile = [&](int k0, int s) {
        #pragma unroll
        for (int i = 0; i < A_ITERS; i++) {
            int idx = tid + i * 256;
            int r = idx >> 3, c = (idx & 7) * 4;
            cp16(&As[(s * BM + r) * LD + c], &Ab[(long)(row0 + r) * K + k0 + c]);
        }
        if (!TRB) {
            constexpr int B_ITERS = BN * BK / (256 * 4);
            #pragma unroll
            for (int i = 0; i < B_ITERS; i++) {
                int idx = tid + i * 256;
                int r = idx >> 3, c = (idx & 7) * 4;
                cp16(&Bs[(s * BN + r) * LD + c], &Bb[(long)(col0 + r) * K + k0 + c]);
            }
        } else {
            // B is [K,N]: coalesced global read, transposed scalar smem store
            constexpr int B_ITERS = BK * BN / (256 * 4);
            #pragma unroll
            for (int i = 0; i < B_ITERS; i++) {
                int idx = tid + i * 256;
                int k = idx / (BN / 4), n = (idx % (BN / 4)) * 4;
                float4 v = *(const float4*)&Bb[(long)(k0 + k) * N + col0 + n];
                Bs[(s * BN + n + 0) * LD + k] = v.x;
                Bs[(s * BN + n + 1) * LD + k] = v.y;
                Bs[(s * BN + n + 2) * LD + k] = v.z;
                Bs[(s * BN + n + 3) * LD + k] = v.w;
            }
        }
        cp_commit();
    };

    const int lane = tid & 31;
    const int w    = tid >> 5;
    const int g    = lane >> 2;
    const int tig  = lane & 3;
    const int rw   = (w % WM) * WTM;
    const int cw   = (w / WM) * WTN;

    float acc[MF][NF][4] = {};

    const int nt = K / BK;
    load_tile(0, 0);

    for (int it = 0; it < nt; it++) {
        int s = it & 1;
        if (it + 1 < nt) { load_tile((it + 1) * BK, s ^ 1); cp_wait<1>(); }
        else             { cp_wait<0>(); }
        __syncthreads();

        #pragma unroll
        for (int kk = 0; kk < BK; kk += 8) {
            uint32_t afr[MF][4], bfr[NF][2];
            #pragma unroll
            for (int mi = 0; mi < MF; mi++) {
                const float* ar0 = &As[(s * BM + rw + mi * 16 + g) * LD + kk + tig];
                const float* ar8 = ar0 + 8 * LD;
                afr[mi][0] = tf32_of(ar0[0]);
                afr[mi][1] = tf32_of(ar8[0]);
                afr[mi][2] = tf32_of(ar0[4]);
                afr[mi][3] = tf32_of(ar8[4]);
            }
            #pragma unroll
            for (int ni = 0; ni < NF; ni++) {
                const float* br = &Bs[(s * BN + cw + ni * 8 + g) * LD + kk + tig];
                bfr[ni][0] = tf32_of(br[0]);
                bfr[ni][1] = tf32_of(br[4]);
            }
            #pragma unroll
            for (int mi = 0; mi < MF; mi++)
                #pragma unroll
                for (int ni = 0; ni < NF; ni++)
                    mma_tf32(acc[mi][ni], afr[mi], bfr[ni]);
        }
        __syncthreads();
    }

    // ---------------- epilogue ----------------
    #pragma unroll
    for (int mi = 0; mi < MF; mi++) {
        #pragma unroll
        for (int ni = 0; ni < NF; ni++) {
            int r_ = row0 + rw + mi * 16 + g;
            int c_ = col0 + cw + ni * 8 + tig * 2;
            float* a4 = acc[mi][ni];
            #pragma unroll
            for (int half = 0; half < 2; half++) {
                int rr = r_ + half * 8;
                float v0 = a4[half * 2 + 0];
                float v1 = a4[half * 2 + 1];

                if (EPI == EPI_SCORES) {
                    // scale only; causal masking happens positionally in softmax
                    float* Cp = C + (long)z * sC;
                    *(float2*)&Cp[(long)rr * N + c_] = make_float2(v0 * 0.125f, v1 * 0.125f);
                } else if (EPI == EPI_QK) {
                    int b = rr >> 10, t = rr & 1023;
                    int h = c_ >> 6,  d = c_ & 63;
                    long o = (((long)(b * NH + h) << 10) + t) * HD + d;
                    *(float2*)&C[o] = make_float2(v0, v1);
                } else if (EPI == EPI_CTX) {
                    int b = z / NH, h = z % NH;
                    long o = ((long)(b * Tseq + rr)) * EMB + h * HD + c_;
                    *(float2*)&C[o] = make_float2(v0, v1);
                } else if (EPI == EPI_RES) {
                    long o = (long)rr * N + c_;
                    float2 rv = *(const float2*)&R[o];
                    *(float2*)&C[o] = make_float2(v0 + rv.x, v1 + rv.y);
                } else if (EPI == EPI_GELU) {
                    const float cst = 0.7978845608028654f;
                    float gl0 = 0.5f * v0 * (1.0f + tanhf(cst * (v0 + 0.044715f * v0 * v0 * v0)));
                    float gl1 = 0.5f * v1 * (1.0f + tanhf(cst * (v1 + 0.044715f * v1 * v1 * v1)));
                    *(float2*)&C[(long)rr * N + c_] = make_float2(gl0, gl1);
                }
            }
        }
    }
}

// ---------------------------------------------------------------------------
// Launch
// ---------------------------------------------------------------------------
extern "C" void kernel_launch(void* const* d_in, const int* in_sizes, int n_in,
                              void* d_out, int out_size) {
    const float* x    = (const float*)d_in[0];
    const float* wq   = (const float*)d_in[1];
    const float* wk   = (const float*)d_in[2];
    const float* wv   = (const float*)d_in[3];
    const float* wo   = (const float*)d_in[4];
    const float* w1   = (const float*)d_in[5];
    const float* w2   = (const float*)d_in[6];
    const float* ln1s = (const float*)d_in[7];
    const float* ln1b = (const float*)d_in[8];
    const float* ln2s = (const float*)d_in[9];
    const float* ln2b = (const float*)d_in[10];
    float* out = (float*)d_out;

    float *h, *q, *k, *v, *sc, *ctx, *x2, *ffn;
    cudaGetSymbolAddress((void**)&h,   g_h);
    cudaGetSymbolAddress((void**)&q,   g_q);
    cudaGetSymbolAddress((void**)&k,   g_k);
    cudaGetSymbolAddress((void**)&v,   g_v);
    cudaGetSymbolAddress((void**)&sc,  g_sc);
    cudaGetSymbolAddress((void**)&ctx, g_ctx);
    cudaGetSymbolAddress((void**)&x2,  g_x2);
    cudaGetSymbolAddress((void**)&ffn, g_ffn);

    constexpr int SM_BIG = 2 * (128 + 128) * 36 * 4;  // 73728 B
    constexpr int SM_CTX = 2 * (128 + 64)  * 36 * 4;  // 55296 B

    cudaFuncSetAttribute(gemm_tc<128,128,2,4,EPI_QK,false>,
                         cudaFuncAttributeMaxDynamicSharedMemorySize, SM_BIG);
    cudaFuncSetAttribute(gemm_tc<128,128,2,4,EPI_SCORES,false>,
                         cudaFuncAttributeMaxDynamicSharedMemorySize, SM_BIG);
    cudaFuncSetAttribute(gemm_tc<128,128,2,4,EPI_RES,false>,
                         cudaFuncAttributeMaxDynamicSharedMemorySize, SM_BIG);
    cudaFuncSetAttribute(gemm_tc<128,128,2,4,EPI_GELU,false>,
                         cudaFuncAttributeMaxDynamicSharedMemorySize, SM_BIG);
    cudaFuncSetAttribute(gemm_tc<128,64,4,2,EPI_CTX,true>,
                         cudaFuncAttributeMaxDynamicSharedMemorySize, SM_CTX);

    // 1) LN1
    layernorm_k<<<NTOK, 256>>>(x, h, ln1s, ln1b);

    // 2-4) QKV projections (fused reshape to [B,H,T,D]) : M=8192, N=768, K=768
    gemm_tc<128,128,2,4,EPI_QK,false><<<dim3(EMB/128, NTOK/128, 1), 256, SM_BIG>>>(
        h, wq, nullptr, q, NTOK, EMB, EMB, 0, 0, 0);
    gemm_tc<128,128,2,4,EPI_QK,false><<<dim3(EMB/128, NTOK/128, 1), 256, SM_BIG>>>(
        h, wk, nullptr, k, NTOK, EMB, EMB, 0, 0, 0);
    gemm_tc<128,128,2,4,EPI_QK,false><<<dim3(EMB/128, NTOK/128, 1), 256, SM_BIG>>>(
        h, wv, nullptr, v, NTOK, EMB, EMB, 0, 0, 0);

    // 5) scores = QK^T/8 (lower-triangular tiles only); batched over B*H
    gemm_tc<128,128,2,4,EPI_SCORES,false><<<dim3(Tseq/128, Tseq/128, Bsz*NH), 256, SM_BIG>>>(
        q, k, nullptr, sc, Tseq, Tseq, HD,
        (long)Tseq * HD, (long)Tseq * HD, (long)Tseq * Tseq);

    // 6) causal softmax (positional mask, zero-fill masked region)
    softmax_k<<<Bsz * NH * Tseq, 256>>>(sc);

    // 7) ctx = attn @ V  (NN: V is [B,H,T,D]); scatter to [B,T,E]
    gemm_tc<128,64,4,2,EPI_CTX,true><<<dim3(1, Tseq/128, Bsz*NH), 256, SM_CTX>>>(
        sc, v, nullptr, ctx, Tseq, HD, Tseq,
        (long)Tseq * Tseq, (long)Tseq * HD, 0);

    // 8) x2 = x + ctx @ Wo^T : M=8192, N=768, K=768
    gemm_tc<128,128,2,4,EPI_RES,false><<<dim3(EMB/128, NTOK/128, 1), 256, SM_BIG>>>(
        ctx, wo, x, x2, NTOK, EMB, EMB, 0, 0, 0);

    // 9) LN2
    layernorm_k<<<NTOK, 256>>>(x2, h, ln2s, ln2b);

    // 10) ffn = gelu(h @ W1^T) : M=8192, N=3072, K=768
    gemm_tc<128,128,2,4,EPI_GELU,false><<<dim3(FFND/128, NTOK/128, 1), 256, SM_BIG>>>(
        h, w1, nullptr, ffn, NTOK, FFND, EMB, 0, 0, 0);

    // 11) out = x2 + ffn @ W2^T : M=8192, N=768, K=3072
    gemm_tc<128,128,2,4,EPI_RES,false><<<dim3(EMB/128, NTOK/128, 1), 256, SM_BIG>>>(
        ffn, w2, x2, out, NTOK, EMB, FFND, 0, 0, 0);
}

// round 5
// speedup vs baseline: 3.4359x; 1.1180x over previous
#include <cuda_runtime.h>
#include <cuda_bf16.h>
#include <math.h>
#include <stdint.h>

// ---------------------------------------------------------------------------
// Problem constants
// ---------------------------------------------------------------------------
#define Bsz   8
#define Tseq  1024
#define EMB   768
#define NH    12
#define HD    64
#define NTOK  (Bsz * Tseq)          // 8192
#define FFND  (4 * EMB)             // 3072

// ---------------------------------------------------------------------------
// Scratch (device globals — allocation-free)
// ---------------------------------------------------------------------------
__device__ float g_h  [NTOK * EMB];                   // LN output
__device__ float g_q  [NTOK * EMB];                   // [B,H,T,D]
__device__ float g_k  [NTOK * EMB];                   // [B,H,T,D]
__device__ float g_v  [NTOK * EMB];                   // [B,H,T,D]
__device__ float g_sc [(long)Bsz * NH * Tseq * Tseq]; // scores / attn
__device__ float g_ctx[NTOK * EMB];                   // [B,T,E]
__device__ float g_x2 [NTOK * EMB];                   // residual after attention
__device__ float g_ffn[NTOK * FFND];                  // gelu(h @ W1^T)

// ---------------------------------------------------------------------------
// cp.async helpers
// ---------------------------------------------------------------------------
__device__ __forceinline__ void cp16(void* dst, const void* src) {
    uint32_t d = (uint32_t)__cvta_generic_to_shared(dst);
    asm volatile("cp.async.ca.shared.global [%0], [%1], 16;" :: "r"(d), "l"(src));
}
__device__ __forceinline__ void cp_commit() {
    asm volatile("cp.async.commit_group;" ::: "memory");
}
template<int N>
__device__ __forceinline__ void cp_wait() {
    asm volatile("cp.async.wait_group %0;" :: "n"(N) : "memory");
}

// ---------------------------------------------------------------------------
// Block reduction helpers (blockDim.x == 256)
// ---------------------------------------------------------------------------
__device__ __forceinline__ float blk_sum(float v, float* s) {
    int t = threadIdx.x;
    #pragma unroll
    for (int o = 16; o; o >>= 1) v += __shfl_xor_sync(0xffffffffu, v, o);
    if ((t & 31) == 0) s[t >> 5] = v;
    __syncthreads();
    if (t < 32) {
        float w = (t < 8) ? s[t] : 0.0f;
        #pragma unroll
        for (int o = 4; o; o >>= 1) w += __shfl_xor_sync(0xffffffffu, w, o);
        if (t == 0) s[0] = w;
    }
    __syncthreads();
    float r = s[0];
    __syncthreads();
    return r;
}

__device__ __forceinline__ float blk_max(float v, float* s) {
    int t = threadIdx.x;
    #pragma unroll
    for (int o = 16; o; o >>= 1) v = fmaxf(v, __shfl_xor_sync(0xffffffffu, v, o));
    if ((t & 31) == 0) s[t >> 5] = v;
    __syncthreads();
    if (t < 32) {
        float w = (t < 8) ? s[t] : -INFINITY;
        #pragma unroll
        for (int o = 4; o; o >>= 1) w = fmaxf(w, __shfl_xor_sync(0xffffffffu, w, o));
        if (t == 0) s[0] = w;
    }
    __syncthreads();
    float r = s[0];
    __syncthreads();
    return r;
}

// ---------------------------------------------------------------------------
// LayerNorm: one block per row of 768
// ---------------------------------------------------------------------------
__global__ void layernorm_k(const float* __restrict__ x, float* __restrict__ o,
                            const float* __restrict__ sc, const float* __restrict__ sh) {
    __shared__ float red[32];
    long row = blockIdx.x;
    const float* p = x + row * EMB;
    float* q = o + row * EMB;
    int t = threadIdx.x;
    float a0 = p[t], a1 = p[t + 256], a2 = p[t + 512];
    float mean = blk_sum(a0 + a1 + a2, red) * (1.0f / EMB);
    float d0 = a0 - mean, d1 = a1 - mean, d2 = a2 - mean;
    float var = blk_sum(d0 * d0 + d1 * d1 + d2 * d2, red) * (1.0f / EMB);
    float rstd = rsqrtf(var + 1e-5f);
    q[t      ] = d0 * rstd * sc[t      ] + sh[t      ];
    q[t + 256] = d1 * rstd * sc[t + 256] + sh[t + 256];
    q[t + 512] = d2 * rstd * sc[t + 512] + sh[t + 512];
}

// ---------------------------------------------------------------------------
// Causal softmax over 1024 columns (in place). One block per row, 256 threads.
// Masks by position; zero-fills masked quads (ctx GEMM K-truncation means the
// masked tail beyond the row's tile is never read, but zero anyway for safety).
// ---------------------------------------------------------------------------
__global__ void softmax_k(float* __restrict__ S) {
    __shared__ float red[32];
    long row = blockIdx.x;
    int rowpos = (int)(row & (Tseq - 1));
    float4* p = (float4*)(S + row * (long)Tseq);
    int t = threadIdx.x;
    int c = 4 * t;
    float4 v = make_float4(-INFINITY, -INFINITY, -INFINITY, -INFINITY);
    bool live = (c <= rowpos);
    if (live) {
        v = p[t];
        if (c + 1 > rowpos) v.y = -INFINITY;
        if (c + 2 > rowpos) v.z = -INFINITY;
        if (c + 3 > rowpos) v.w = -INFINITY;
    }
    float m = blk_max(fmaxf(fmaxf(v.x, v.y), fmaxf(v.z, v.w)), red);
    float e0 = __expf(v.x - m), e1 = __expf(v.y - m);
    float e2 = __expf(v.z - m), e3 = __expf(v.w - m);
    float z = blk_sum(e0 + e1 + e2 + e3, red);
    float inv = 1.0f / z;
    p[t] = make_float4(e0 * inv, e1 * inv, e2 * inv, e3 * inv);
}

// ---------------------------------------------------------------------------
// Tensor-core GEMM (tf32 mma.sync m16n8k8), 2-stage cp.async pipeline.
//   TRB=false:  C[m,n] = sum_k A[m,k] * B[n,k]   (NT; both K-contiguous)
//   TRB=true :  C[m,n] = sum_k A[m,k] * B[k,n]   (NN; B is [K,N] row-major)
// CAUSALK: cap K at row0+BM (attn ctx GEMM — tail of A row is zeros).
// CTA tile BM x BN x 32, 256 threads = 8 warps (WM x WN). 2 CTAs/SM enforced.
// ---------------------------------------------------------------------------
#define EPI_SCORES 1
#define EPI_QK     2
#define EPI_CTX    4
#define EPI_RES    5
#define EPI_GELU   6

__device__ __forceinline__ uint32_t tf32_of(float x) {
    uint32_t r;
    asm("cvt.rna.tf32.f32 %0, %1;" : "=r"(r) : "f"(x));
    return r;
}

__device__ __forceinline__ void mma_tf32(float* d, const uint32_t* a, const uint32_t* b) {
    asm volatile(
        "mma.sync.aligned.m16n8k8.row.col.f32.tf32.tf32.f32 "
        "{%0,%1,%2,%3}, {%4,%5,%6,%7}, {%8,%9}, {%0,%1,%2,%3};"
        : "+f"(d[0]), "+f"(d[1]), "+f"(d[2]), "+f"(d[3])
        : "r"(a[0]), "r"(a[1]), "r"(a[2]), "r"(a[3]), "r"(b[0]), "r"(b[1]));
}

template<int BM, int BN, int WM, int WN, int EPI, bool TRB, bool CAUSALK>
__global__ void __launch_bounds__(256, 2)
gemm_tc(const float* __restrict__ A, const float* __restrict__ Bm,
        const float* __restrict__ R, float* __restrict__ C,
        int M, int N, int K, long sA, long sB, long sC) {
    constexpr int BK  = 32;
    constexpr int PAD = 4;
    constexpr int LD  = BK + PAD;        // 36 floats -> 144B rows (16B aligned)
    constexpr int WTM = BM / WM;
    constexpr int WTN = BN / WN;
    constexpr int MF  = WTM / 16;
    constexpr int NF  = WTN / 8;

    const int tid  = threadIdx.x;
    const int z    = blockIdx.z;
    const int row0 = blockIdx.y * BM;
    const int col0 = blockIdx.x * BN;

    if (EPI == EPI_SCORES && blockIdx.x > blockIdx.y) return;  // masked tile: skip

    extern __shared__ float smem[];
    float* As = smem;                    // [2][BM][LD]
    float* Bs = smem + 2 * BM * LD;      // [2][BN][LD]

    const float* Ab = A + (long)z * sA;
    const float* Bb = Bm + (long)z * sB;

    constexpr int A_ITERS = BM * BK / (256 * 4);

    auto load_tile = [&](int k0, int s) {
        #pragma unroll
        for (int i = 0; i < A_ITERS; i++) {
            int idx = tid + i * 256;
            int r = idx >> 3, c = (idx & 7) * 4;
            cp16(&As[(s * BM + r) * LD + c], &Ab[(long)(row0 + r) * K + k0 + c]);
        }
        if (!TRB) {
            constexpr int B_ITERS = BN * BK / (256 * 4);
            #pragma unroll
            for (int i = 0; i < B_ITERS; i++) {
                int idx = tid + i * 256;
                int r = idx >> 3, c = (idx & 7) * 4;
                cp16(&Bs[(s * BN + r) * LD + c], &Bb[(long)(col0 + r) * K + k0 + c]);
            }
        } else {
            // B is [K,N]: coalesced global read, transposed scalar smem store
            constexpr int B_ITERS = BK * BN / (256 * 4);
            #pragma unroll
            for (int i = 0; i < B_ITERS; i++) {
                int idx = tid + i * 256;
                int k = idx / (BN / 4), n = (idx % (BN / 4)) * 4;
                float4 v = *(const float4*)&Bb[(long)(k0 + k) * N + col0 + n];
                Bs[(s * BN + n + 0) * LD + k] = v.x;
                Bs[(s * BN + n + 1) * LD + k] = v.y;
                Bs[(s * BN + n + 2) * LD + k] = v.z;
                Bs[(s * BN + n + 3) * LD + k] = v.w;
            }
        }
        cp_commit();
    };

    const int lane = tid & 31;
    const int w    = tid >> 5;
    const int g    = lane >> 2;
    const int tig  = lane & 3;
    const int rw   = (w % WM) * WTM;
    const int cw   = (w / WM) * WTN;

    float acc[MF][NF][4] = {};

    // causal K truncation: rows in this tile only attend k < row0+BM
    const int Keff = CAUSALK ? min(K, row0 + BM) : K;
    const int nt = Keff / BK;
    load_tile(0, 0);

    for (int it = 0; it < nt; it++) {
        int s = it & 1;
        if (it + 1 < nt) { load_tile((it + 1) * BK, s ^ 1); cp_wait<1>(); }
        else             { cp_wait<0>(); }
        __syncthreads();

        #pragma unroll
        for (int kk = 0; kk < BK; kk += 8) {
            uint32_t afr[MF][4], bfr[NF][2];
            #pragma unroll
            for (int mi = 0; mi < MF; mi++) {
                const float* ar0 = &As[(s * BM + rw + mi * 16 + g) * LD + kk + tig];
                const float* ar8 = ar0 + 8 * LD;
                afr[mi][0] = tf32_of(ar0[0]);
                afr[mi][1] = tf32_of(ar8[0]);
                afr[mi][2] = tf32_of(ar0[4]);
                afr[mi][3] = tf32_of(ar8[4]);
            }
            #pragma unroll
            for (int ni = 0; ni < NF; ni++) {
                const float* br = &Bs[(s * BN + cw + ni * 8 + g) * LD + kk + tig];
                bfr[ni][0] = tf32_of(br[0]);
                bfr[ni][1] = tf32_of(br[4]);
            }
            #pragma unroll
            for (int mi = 0; mi < MF; mi++)
                #pragma unroll
                for (int ni = 0; ni < NF; ni++)
                    mma_tf32(acc[mi][ni], afr[mi], bfr[ni]);
        }
        __syncthreads();
    }

    // ---------------- epilogue ----------------
    #pragma unroll
    for (int mi = 0; mi < MF; mi++) {
        #pragma unroll
        for (int ni = 0; ni < NF; ni++) {
            int r_ = row0 + rw + mi * 16 + g;
            int c_ = col0 + cw + ni * 8 + tig * 2;
            float* a4 = acc[mi][ni];
            #pragma unroll
            for (int half = 0; half < 2; half++) {
                int rr = r_ + half * 8;
                float v0 = a4[half * 2 + 0];
                float v1 = a4[half * 2 + 1];

                if (EPI == EPI_SCORES) {
                    // scale only; causal masking happens positionally in softmax
                    float* Cp = C + (long)z * sC;
                    *(float2*)&Cp[(long)rr * N + c_] = make_float2(v0 * 0.125f, v1 * 0.125f);
                } else if (EPI == EPI_QK) {
                    int b = rr >> 10, t = rr & 1023;
                    int h = c_ >> 6,  d = c_ & 63;
                    long o = (((long)(b * NH + h) << 10) + t) * HD + d;
                    *(float2*)&C[o] = make_float2(v0, v1);
                } else if (EPI == EPI_CTX) {
                    int b = z / NH, h = z % NH;
                    long o = ((long)(b * Tseq + rr)) * EMB + h * HD + c_;
                    *(float2*)&C[o] = make_float2(v0, v1);
                } else if (EPI == EPI_RES) {
                    long o = (long)rr * N + c_;
                    float2 rv = *(const float2*)&R[o];
                    *(float2*)&C[o] = make_float2(v0 + rv.x, v1 + rv.y);
                } else if (EPI == EPI_GELU) {
                    const float cst = 0.7978845608028654f;
                    float gl0 = 0.5f * v0 * (1.0f + tanhf(cst * (v0 + 0.044715f * v0 * v0 * v0)));
                    float gl1 = 0.5f * v1 * (1.0f + tanhf(cst * (v1 + 0.044715f * v1 * v1 * v1)));
                    *(float2*)&C[(long)rr * N + c_] = make_float2(gl0, gl1);
                }
            }
        }
    }
}

// ---------------------------------------------------------------------------
// Launch
// ---------------------------------------------------------------------------
extern "C" void kernel_launch(void* const* d_in, const int* in_sizes, int n_in,
                              void* d_out, int out_size) {
    const float* x    = (const float*)d_in[0];
    const float* wq   = (const float*)d_in[1];
    const float* wk   = (const float*)d_in[2];
    const float* wv   = (const float*)d_in[3];
    const float* wo   = (const float*)d_in[4];
    const float* w1   = (const float*)d_in[5];
    const float* w2   = (const float*)d_in[6];
    const float* ln1s = (const float*)d_in[7];
    const float* ln1b = (const float*)d_in[8];
    const float* ln2s = (const float*)d_in[9];
    const float* ln2b = (const float*)d_in[10];
    float* out = (float*)d_out;

    float *h, *q, *k, *v, *sc, *ctx, *x2, *ffn;
    cudaGetSymbolAddress((void**)&h,   g_h);
    cudaGetSymbolAddress((void**)&q,   g_q);
    cudaGetSymbolAddress((void**)&k,   g_k);
    cudaGetSymbolAddress((void**)&v,   g_v);
    cudaGetSymbolAddress((void**)&sc,  g_sc);
    cudaGetSymbolAddress((void**)&ctx, g_ctx);
    cudaGetSymbolAddress((void**)&x2,  g_x2);
    cudaGetSymbolAddress((void**)&ffn, g_ffn);

    constexpr int SM_BIG = 2 * (128 + 128) * 36 * 4;  // 73728 B
    constexpr int SM_CTX = 2 * (128 + 64)  * 36 * 4;  // 55296 B

    cudaFuncSetAttribute(gemm_tc<128,128,2,4,EPI_QK,false,false>,
                         cudaFuncAttributeMaxDynamicSharedMemorySize, SM_BIG);
    cudaFuncSetAttribute(gemm_tc<128,128,2,4,EPI_SCORES,false,false>,
                         cudaFuncAttributeMaxDynamicSharedMemorySize, SM_BIG);
    cudaFuncSetAttribute(gemm_tc<128,128,2,4,EPI_RES,false,false>,
                         cudaFuncAttributeMaxDynamicSharedMemorySize, SM_BIG);
    cudaFuncSetAttribute(gemm_tc<128,128,2,4,EPI_GELU,false,false>,
                         cudaFuncAttributeMaxDynamicSharedMemorySize, SM_BIG);
    cudaFuncSetAttribute(gemm_tc<128,64,4,2,EPI_CTX,true,true>,
                         cudaFuncAttributeMaxDynamicSharedMemorySize, SM_CTX);

    // 1) LN1
    layernorm_k<<<NTOK, 256>>>(x, h, ln1s, ln1b);

    // 2-4) QKV projections (fused reshape to [B,H,T,D]) : M=8192, N=768, K=768
    gemm_tc<128,128,2,4,EPI_QK,false,false><<<dim3(EMB/128, NTOK/128, 1), 256, SM_BIG>>>(
        h, wq, nullptr, q, NTOK, EMB, EMB, 0, 0, 0);
    gemm_tc<128,128,2,4,EPI_QK,false,false><<<dim3(EMB/128, NTOK/128, 1), 256, SM_BIG>>>(
        h, wk, nullptr, k, NTOK, EMB, EMB, 0, 0, 0);
    gemm_tc<128,128,2,4,EPI_QK,false,false><<<dim3(EMB/128, NTOK/128, 1), 256, SM_BIG>>>(
        h, wv, nullptr, v, NTOK, EMB, EMB, 0, 0, 0);

    // 5) scores = QK^T/8 (lower-triangular tiles only); batched over B*H
    gemm_tc<128,128,2,4,EPI_SCORES,false,false><<<dim3(Tseq/128, Tseq/128, Bsz*NH), 256, SM_BIG>>>(
        q, k, nullptr, sc, Tseq, Tseq, HD,
        (long)Tseq * HD, (long)Tseq * HD, (long)Tseq * Tseq);

    // 6) causal softmax (positional mask, zero-fill masked region)
    softmax_k<<<Bsz * NH * Tseq, 256>>>(sc);

    // 7) ctx = attn @ V  (NN: V is [B,H,T,D], causal K-truncation); scatter to [B,T,E]
    gemm_tc<128,64,4,2,EPI_CTX,true,true><<<dim3(1, Tseq/128, Bsz*NH), 256, SM_CTX>>>(
        sc, v, nullptr, ctx, Tseq, HD, Tseq,
        (long)Tseq * Tseq, (long)Tseq * HD, 0);

    // 8) x2 = x + ctx @ Wo^T : M=8192, N=768, K=768
    gemm_tc<128,128,2,4,EPI_RES,false,false><<<dim3(EMB/128, NTOK/128, 1), 256, SM_BIG>>>(
        ctx, wo, x, x2, NTOK, EMB, EMB, 0, 0, 0);

    // 9) LN2
    layernorm_k<<<NTOK, 256>>>(x2, h, ln2s, ln2b);

    // 10) ffn = gelu(h @ W1^T) : M=8192, N=3072, K=768
    gemm_tc<128,128,2,4,EPI_GELU,false,false><<<dim3(FFND/128, NTOK/128, 1), 256, SM_BIG>>>(
        h, w1, nullptr, ffn, NTOK, FFND, EMB, 0, 0, 0);

    // 11) out = x2 + ffn @ W2^T : M=8192, N=768, K=3072
    gemm_tc<128,128,2,4,EPI_RES,false,false><<<dim3(EMB/128, NTOK/128, 1), 256, SM_BIG>>>(
        ffn, w2, x2, out, NTOK, EMB, FFND, 0, 0, 0);
}

// round 6
// speedup vs baseline: 6.1653x; 1.7944x over previous
#include <cuda_runtime.h>
#include <cuda_fp16.h>
#include <math.h>
#include <stdint.h>

// ---------------------------------------------------------------------------
// Problem constants
// ---------------------------------------------------------------------------
#define Bsz   8
#define Tseq  1024
#define EMB   768
#define NH    12
#define HD    64
#define NTOK  (Bsz * Tseq)          // 8192
#define FFND  (4 * EMB)             // 3072

// ---------------------------------------------------------------------------
// Scratch (device globals — allocation-free)
// ---------------------------------------------------------------------------
__device__ __half g_h16  [NTOK * EMB];                   // LN output (fp16)
__device__ __half g_q16  [NTOK * EMB];                   // [B,H,T,D]
__device__ __half g_k16  [NTOK * EMB];                   // [B,H,T,D]
__device__ __half g_v16  [NTOK * EMB];                   // [B,H,T,D]
__device__ __half g_sc16 [(long)Bsz * NH * Tseq * Tseq]; // scores / probs (fp16)
__device__ __half g_ctx16[NTOK * EMB];                   // [B,T,E]
__device__ __half g_ffn16[NTOK * FFND];                  // gelu(h @ W1^T)
__device__ float  g_x2   [NTOK * EMB];                   // fp32 residual stream
// fp16 weight copies
__device__ __half g_wq16[EMB * EMB];
__device__ __half g_wk16[EMB * EMB];
__device__ __half g_wv16[EMB * EMB];
__device__ __half g_wo16[EMB * EMB];
__device__ __half g_w116[FFND * EMB];
__device__ __half g_w216[EMB * FFND];

// ---------------------------------------------------------------------------
// PTX helpers
// ---------------------------------------------------------------------------
__device__ __forceinline__ void cp16s(uint32_t dst, const void* src) {
    asm volatile("cp.async.ca.shared.global [%0], [%1], 16;" :: "r"(dst), "l"(src));
}
__device__ __forceinline__ void cp_commit() {
    asm volatile("cp.async.commit_group;" ::: "memory");
}
template<int N>
__device__ __forceinline__ void cp_wait() {
    asm volatile("cp.async.wait_group %0;" :: "n"(N) : "memory");
}
__device__ __forceinline__ uint32_t sw128(uint32_t o) {   // Swizzle<3,4,3> on 128B rows
    return o ^ ((o >> 3) & 0x70);
}
__device__ __forceinline__ void ldsm4(uint32_t* r, uint32_t addr) {
    asm volatile("ldmatrix.sync.aligned.m8n8.x4.shared.b16 {%0,%1,%2,%3}, [%4];"
        : "=r"(r[0]), "=r"(r[1]), "=r"(r[2]), "=r"(r[3]) : "r"(addr));
}
__device__ __forceinline__ void ldsm4t(uint32_t* r, uint32_t addr) {
    asm volatile("ldmatrix.sync.aligned.m8n8.x4.trans.shared.b16 {%0,%1,%2,%3}, [%4];"
        : "=r"(r[0]), "=r"(r[1]), "=r"(r[2]), "=r"(r[3]) : "r"(addr));
}
__device__ __forceinline__ void mma16816(float* d, const uint32_t* a, const uint32_t* b) {
    asm volatile(
        "mma.sync.aligned.m16n8k16.row.col.f32.f16.f16.f32 "
        "{%0,%1,%2,%3}, {%4,%5,%6,%7}, {%8,%9}, {%0,%1,%2,%3};"
        : "+f"(d[0]), "+f"(d[1]), "+f"(d[2]), "+f"(d[3])
        : "r"(a[0]), "r"(a[1]), "r"(a[2]), "r"(a[3]), "r"(b[0]), "r"(b[1]));
}

// ---------------------------------------------------------------------------
// Block reduction helpers (blockDim.x == 256)
// ---------------------------------------------------------------------------
__device__ __forceinline__ float blk_sum(float v, float* s) {
    int t = threadIdx.x;
    #pragma unroll
    for (int o = 16; o; o >>= 1) v += __shfl_xor_sync(0xffffffffu, v, o);
    if ((t & 31) == 0) s[t >> 5] = v;
    __syncthreads();
    if (t < 32) {
        float w = (t < 8) ? s[t] : 0.0f;
        #pragma unroll
        for (int o = 4; o; o >>= 1) w += __shfl_xor_sync(0xffffffffu, w, o);
        if (t == 0) s[0] = w;
    }
    __syncthreads();
    float r = s[0];
    __syncthreads();
    return r;
}
__device__ __forceinline__ float blk_max(float v, float* s) {
    int t = threadIdx.x;
    #pragma unroll
    for (int o = 16; o; o >>= 1) v = fmaxf(v, __shfl_xor_sync(0xffffffffu, v, o));
    if ((t & 31) == 0) s[t >> 5] = v;
    __syncthreads();
    if (t < 32) {
        float w = (t < 8) ? s[t] : -INFINITY;
        #pragma unroll
        for (int o = 4; o; o >>= 1) w = fmaxf(w, __shfl_xor_sync(0xffffffffu, w, o));
        if (t == 0) s[0] = w;
    }
    __syncthreads();
    float r = s[0];
    __syncthreads();
    return r;
}

// ---------------------------------------------------------------------------
// fp32 -> fp16 converter (weights). n % 1024 == 0.
// ---------------------------------------------------------------------------
__global__ void f2h_k(const float* __restrict__ s, __half* __restrict__ d) {
    int i = (blockIdx.x * 256 + threadIdx.x) * 4;
    float4 v = *(const float4*)(s + i);
    __half2 a = __floats2half2_rn(v.x, v.y);
    __half2 b = __floats2half2_rn(v.z, v.w);
    *(__half2*)(d + i)     = a;
    *(__half2*)(d + i + 2) = b;
}

// ---------------------------------------------------------------------------
// LayerNorm: fp32 in, fp16 out. One block per row of 768.
// ---------------------------------------------------------------------------
__global__ void layernorm_k(const float* __restrict__ x, __half* __restrict__ o,
                            const float* __restrict__ sc, const float* __restrict__ sh) {
    __shared__ float red[32];
    long row = blockIdx.x;
    const float* p = x + row * EMB;
    __half* q = o + row * EMB;
    int t = threadIdx.x;
    float a0 = p[t], a1 = p[t + 256], a2 = p[t + 512];
    float mean = blk_sum(a0 + a1 + a2, red) * (1.0f / EMB);
    float d0 = a0 - mean, d1 = a1 - mean, d2 = a2 - mean;
    float var = blk_sum(d0 * d0 + d1 * d1 + d2 * d2, red) * (1.0f / EMB);
    float rstd = rsqrtf(var + 1e-5f);
    q[t      ] = __float2half_rn(d0 * rstd * sc[t      ] + sh[t      ]);
    q[t + 256] = __float2half_rn(d1 * rstd * sc[t + 256] + sh[t + 256]);
    q[t + 512] = __float2half_rn(d2 * rstd * sc[t + 512] + sh[t + 512]);
}

// ---------------------------------------------------------------------------
// Causal softmax over 1024 fp16 columns (in place), fp32 math.
// Masks positionally; writes zeros in masked region (read by ctx GEMM).
// ---------------------------------------------------------------------------
__global__ void softmax_k(__half* __restrict__ S) {
    __shared__ float red[32];
    long row = blockIdx.x;
    int rowpos = (int)(row & (Tseq - 1));
    __half2* p = (__half2*)(S + row * (long)Tseq);
    int t = threadIdx.x;
    int c = 4 * t;
    float v0 = -INFINITY, v1 = -INFINITY, v2 = -INFINITY, v3 = -INFINITY;
    if (c <= rowpos) {
        float2 fa = __half22float2(p[2 * t]);
        float2 fb = __half22float2(p[2 * t + 1]);
        v0 = fa.x;
        v1 = (c + 1 <= rowpos) ? fa.y : -INFINITY;
        v2 = (c + 2 <= rowpos) ? fb.x : -INFINITY;
        v3 = (c + 3 <= rowpos) ? fb.y : -INFINITY;
    }
    float m = blk_max(fmaxf(fmaxf(v0, v1), fmaxf(v2, v3)), red);
    float e0 = __expf(v0 - m), e1 = __expf(v1 - m);
    float e2 = __expf(v2 - m), e3 = __expf(v3 - m);
    float z = blk_sum(e0 + e1 + e2 + e3, red);
    float inv = 1.0f / z;
    p[2 * t]     = __floats2half2_rn(e0 * inv, e1 * inv);
    p[2 * t + 1] = __floats2half2_rn(e2 * inv, e3 * inv);
}

// ---------------------------------------------------------------------------
// fp16 tensor-core GEMM (m16n8k16, ldmatrix, SW128 swizzle, 3-stage cp.async)
//   TRB=false: C[m,n] = sum_k A[m,k]*B[n,k]   (NT; both K-contiguous fp16)
//   TRB=true : C[m,n] = sum_k A[m,k]*B[k,n]   (NN; B rows=k, BN==64 required)
// CAUSALK: cap K at row0+BM. 256 threads = 8 warps (WM x WN), 2 CTAs/SM.
// ---------------------------------------------------------------------------
#define EPI_SCORES 1
#define EPI_QK     2
#define EPI_CTX    4
#define EPI_RES    5
#define EPI_GELU   6

template<int BM, int BN, int WM, int WN, int EPI, bool TRB, bool CAUSALK>
__global__ void __launch_bounds__(256, 2)
gemm_h(const __half* __restrict__ A, const __half* __restrict__ Bm,
       const float* __restrict__ R, void* __restrict__ Cv,
       int M, int N, int K, long sA, long sB, long sC) {
    constexpr int BK  = 64;                       // halfs; 128B rows
    constexpr int WTM = BM / WM, WTN = BN / WN;
    constexpr int MF  = WTM / 16, NF = WTN / 8;
    constexpr int A_STG = BM * BK * 2;            // bytes per stage
    constexpr int B_STG = (TRB ? BK * BN : BN * BK) * 2;
    static_assert(!TRB || BN == 64, "TRB requires 128B B rows");

    const int tid  = threadIdx.x;
    const int z    = blockIdx.z;
    const int row0 = blockIdx.y * BM;
    const int col0 = blockIdx.x * BN;

    if (EPI == EPI_SCORES && blockIdx.x > blockIdx.y) return;  // masked tile

    extern __shared__ char smraw[];
    const uint32_t smA = (uint32_t)__cvta_generic_to_shared(smraw);
    const uint32_t smB = smA + 3 * A_STG;

    const __half* Ab = A + (long)z * sA;
    const __half* Bb = Bm + (long)z * sB;

    auto load_tile = [&](int k0, int s) {
        uint32_t aB = smA + s * A_STG;
        #pragma unroll
        for (int i = 0; i < BM * 8 / 256; i++) {
            int idx = tid + i * 256, r = idx >> 3, c = idx & 7;
            cp16s(aB + sw128(r * 128 + c * 16), Ab + (long)(row0 + r) * K + k0 + c * 8);
        }
        uint32_t bB = smB + s * B_STG;
        if (!TRB) {
            #pragma unroll
            for (int i = 0; i < BN * 8 / 256; i++) {
                int idx = tid + i * 256, r = idx >> 3, c = idx & 7;
                cp16s(bB + sw128(r * 128 + c * 16), Bb + (long)(col0 + r) * K + k0 + c * 8);
            }
        } else {
            #pragma unroll
            for (int i = 0; i < BK * 8 / 256; i++) {
                int idx = tid + i * 256, r = idx >> 3, c = idx & 7;  // r = k row
                cp16s(bB + sw128(r * 128 + c * 16), Bb + (long)(k0 + r) * N + col0 + c * 8);
            }
        }
        cp_commit();
    };

    const int lane = tid & 31, w = tid >> 5;
    const int g = lane >> 2, tig = lane & 3;
    const int rw = (w % WM) * WTM, cw = (w / WM) * WTN;
    const int aRow = (lane & 7) + ((lane >> 3) & 1) * 8;   // A: mats (m0,k0)(m8,k0)(m0,k8)(m8,k8)
    const int aChk = lane >> 4;
    const int bRow = (lane & 7) + (lane >> 4) * 8;         // B NT: (nA,k0)(nA,k8)(nB,k0)(nB,k8)
    const int bChk = (lane >> 3) & 1;
    const int vRow = (lane & 7) + ((lane >> 3) & 1) * 8;   // B TRB: (k0,nA)(k8,nA)(k0,nB)(k8,nB)
    const int vChk = lane >> 4;

    float acc[MF][NF][4] = {};

    const int Keff = CAUSALK ? min(K, row0 + BM) : K;
    const int nt = Keff / BK;

    load_tile(0, 0);
    if (nt > 1) load_tile(BK, 1); else cp_commit();

    for (int it = 0; it < nt; it++) {
        int s = it % 3;
        if (it + 2 < nt) load_tile((it + 2) * BK, (it + 2) % 3); else cp_commit();
        cp_wait<2>();
        __syncthreads();
        uint32_t aS = smA + s * A_STG, bS = smB + s * B_STG;

        #pragma unroll
        for (int kk = 0; kk < BK; kk += 16) {
            uint32_t afr[MF][4];
            #pragma unroll
            for (int mi = 0; mi < MF; mi++)
                ldsm4(afr[mi], aS + sw128((rw + mi * 16 + aRow) * 128 + ((kk >> 3) + aChk) * 16));
            uint32_t bfr[NF][2];
            #pragma unroll
            for (int j = 0; j < NF / 2; j++) {
                uint32_t r4[4];
                if (!TRB)
                    ldsm4(r4, bS + sw128((cw + j * 16 + bRow) * 128 + ((kk >> 3) + bChk) * 16));
                else
                    ldsm4t(r4, bS + sw128((kk + vRow) * 128 + ((cw >> 3) + 2 * j + vChk) * 16));
                bfr[2*j][0] = r4[0]; bfr[2*j][1] = r4[1];
                bfr[2*j+1][0] = r4[2]; bfr[2*j+1][1] = r4[3];
            }
            #pragma unroll
            for (int mi = 0; mi < MF; mi++)
                #pragma unroll
                for (int ni = 0; ni < NF; ni++)
                    mma16816(acc[mi][ni], afr[mi], bfr[ni]);
        }
        __syncthreads();
    }

    // ---------------- epilogue ----------------
    #pragma unroll
    for (int mi = 0; mi < MF; mi++) {
        #pragma unroll
        for (int ni = 0; ni < NF; ni++) {
            int r_ = row0 + rw + mi * 16 + g;
            int c_ = col0 + cw + ni * 8 + tig * 2;
            float* a4 = acc[mi][ni];
            #pragma unroll
            for (int half = 0; half < 2; half++) {
                int rr = r_ + half * 8;
                float v0 = a4[half * 2 + 0];
                float v1 = a4[half * 2 + 1];

                if (EPI == EPI_SCORES) {
                    __half* Cp = (__half*)Cv + (long)z * sC;
                    *(__half2*)&Cp[(long)rr * N + c_] =
                        __floats2half2_rn(v0 * 0.125f, v1 * 0.125f);
                } else if (EPI == EPI_QK) {
                    __half* Cp = (__half*)Cv;
                    int b = rr >> 10, t = rr & 1023;
                    int h = c_ >> 6,  d = c_ & 63;
                    long o = (((long)(b * NH + h) << 10) + t) * HD + d;
                    *(__half2*)&Cp[o] = __floats2half2_rn(v0, v1);
                } else if (EPI == EPI_CTX) {
                    __half* Cp = (__half*)Cv;
                    int b = z / NH, h = z % NH;
                    long o = ((long)(b * Tseq + rr)) * EMB + h * HD + c_;
                    *(__half2*)&Cp[o] = __floats2half2_rn(v0, v1);
                } else if (EPI == EPI_RES) {
                    float* Cp = (float*)Cv;
                    long o = (long)rr * N + c_;
                    float2 rv = *(const float2*)&R[o];
                    *(float2*)&Cp[o] = make_float2(v0 + rv.x, v1 + rv.y);
                } else if (EPI == EPI_GELU) {
                    __half* Cp = (__half*)Cv;
                    const float cst = 0.7978845608028654f;
                    float gl0 = 0.5f * v0 * (1.0f + tanhf(cst * (v0 + 0.044715f * v0 * v0 * v0)));
                    float gl1 = 0.5f * v1 * (1.0f + tanhf(cst * (v1 + 0.044715f * v1 * v1 * v1)));
                    *(__half2*)&Cp[(long)rr * N + c_] = __floats2half2_rn(gl0, gl1);
                }
            }
        }
    }
}

// ---------------------------------------------------------------------------
// Launch
// ---------------------------------------------------------------------------
extern "C" void kernel_launch(void* const* d_in, const int* in_sizes, int n_in,
                              void* d_out, int out_size) {
    const float* x    = (const float*)d_in[0];
    const float* wq   = (const float*)d_in[1];
    const float* wk   = (const float*)d_in[2];
    const float* wv   = (const float*)d_in[3];
    const float* wo   = (const float*)d_in[4];
    const float* w1   = (const float*)d_in[5];
    const float* w2   = (const float*)d_in[6];
    const float* ln1s = (const float*)d_in[7];
    const float* ln1b = (const float*)d_in[8];
    const float* ln2s = (const float*)d_in[9];
    const float* ln2b = (const float*)d_in[10];
    float* out = (float*)d_out;

    __half *h16, *q16, *k16, *v16, *sc16, *ctx16, *ffn16;
    __half *wq16, *wk16, *wv16, *wo16, *w116, *w216;
    float* x2;
    cudaGetSymbolAddress((void**)&h16,   g_h16);
    cudaGetSymbolAddress((void**)&q16,   g_q16);
    cudaGetSymbolAddress((void**)&k16,   g_k16);
    cudaGetSymbolAddress((void**)&v16,   g_v16);
    cudaGetSymbolAddress((void**)&sc16,  g_sc16);
    cudaGetSymbolAddress((void**)&ctx16, g_ctx16);
    cudaGetSymbolAddress((void**)&ffn16, g_ffn16);
    cudaGetSymbolAddress((void**)&x2,    g_x2);
    cudaGetSymbolAddress((void**)&wq16,  g_wq16);
    cudaGetSymbolAddress((void**)&wk16,  g_wk16);
    cudaGetSymbolAddress((void**)&wv16,  g_wv16);
    cudaGetSymbolAddress((void**)&wo16,  g_wo16);
    cudaGetSymbolAddress((void**)&w116,  g_w116);
    cudaGetSymbolAddress((void**)&w216,  g_w216);

    constexpr int SM_NT  = 3 * (128 * 64 + 128 * 64) * 2;  // 98304 B
    constexpr int SM_CTX = 3 * (128 * 64 + 64 * 64) * 2;   // 73728 B

    cudaFuncSetAttribute(gemm_h<128,128,2,4,EPI_QK,false,false>,
                         cudaFuncAttributeMaxDynamicSharedMemorySize, SM_NT);
    cudaFuncSetAttribute(gemm_h<128,128,2,4,EPI_SCORES,false,false>,
                         cudaFuncAttributeMaxDynamicSharedMemorySize, SM_NT);
    cudaFuncSetAttribute(gemm_h<128,128,2,4,EPI_RES,false,false>,
                         cudaFuncAttributeMaxDynamicSharedMemorySize, SM_NT);
    cudaFuncSetAttribute(gemm_h<128,128,2,4,EPI_GELU,false,false>,
                         cudaFuncAttributeMaxDynamicSharedMemorySize, SM_NT);
    cudaFuncSetAttribute(gemm_h<128,64,2,4,EPI_CTX,true,true>,
                         cudaFuncAttributeMaxDynamicSharedMemorySize, SM_CTX);

    // 0) weight fp32 -> fp16 copies
    f2h_k<<<EMB * EMB / 1024, 256>>>(wq, wq16);
    f2h_k<<<EMB * EMB / 1024, 256>>>(wk, wk16);
    f2h_k<<<EMB * EMB / 1024, 256>>>(wv, wv16);
    f2h_k<<<EMB * EMB / 1024, 256>>>(wo, wo16);
    f2h_k<<<FFND * EMB / 1024, 256>>>(w1, w116);
    f2h_k<<<EMB * FFND / 1024, 256>>>(w2, w216);

    // 1) LN1 (fp32 -> fp16)
    layernorm_k<<<NTOK, 256>>>(x, h16, ln1s, ln1b);

    // 2-4) QKV projections -> [B,H,T,D] fp16 : M=8192, N=768, K=768
    gemm_h<128,128,2,4,EPI_QK,false,false><<<dim3(EMB/128, NTOK/128, 1), 256, SM_NT>>>(
        h16, wq16, nullptr, q16, NTOK, EMB, EMB, 0, 0, 0);
    gemm_h<128,128,2,4,EPI_QK,false,false><<<dim3(EMB/128, NTOK/128, 1), 256, SM_NT>>>(
        h16, wk16, nullptr, k16, NTOK, EMB, EMB, 0, 0, 0);
    gemm_h<128,128,2,4,EPI_QK,false,false><<<dim3(EMB/128, NTOK/128, 1), 256, SM_NT>>>(
        h16, wv16, nullptr, v16, NTOK, EMB, EMB, 0, 0, 0);

    // 5) scores = QK^T/8 (lower-triangular tiles only); K=64, batched over B*H
    gemm_h<128,128,2,4,EPI_SCORES,false,false><<<dim3(Tseq/128, Tseq/128, Bsz*NH), 256, SM_NT>>>(
        q16, k16, nullptr, sc16, Tseq, Tseq, HD,
        (long)Tseq * HD, (long)Tseq * HD, (long)Tseq * Tseq);

    // 6) causal softmax (fp16 in/out, fp32 math)
    softmax_k<<<Bsz * NH * Tseq, 256>>>(sc16);

    // 7) ctx = attn @ V  (NN via ldmatrix.trans; causal K-truncation)
    gemm_h<128,64,2,4,EPI_CTX,true,true><<<dim3(1, Tseq/128, Bsz*NH), 256, SM_CTX>>>(
        sc16, v16, nullptr, ctx16, Tseq, HD, Tseq,
        (long)Tseq * Tseq, (long)Tseq * HD, 0);

    // 8) x2 = x + ctx @ Wo^T (fp32 residual) : M=8192, N=768, K=768
    gemm_h<128,128,2,4,EPI_RES,false,false><<<dim3(EMB/128, NTOK/128, 1), 256, SM_NT>>>(
        ctx16, wo16, x, x2, NTOK, EMB, EMB, 0, 0, 0);

    // 9) LN2 (fp32 -> fp16)
    layernorm_k<<<NTOK, 256>>>(x2, h16, ln2s, ln2b);

    // 10) ffn = gelu(h @ W1^T) fp16 : M=8192, N=3072, K=768
    gemm_h<128,128,2,4,EPI_GELU,false,false><<<dim3(FFND/128, NTOK/128, 1), 256, SM_NT>>>(
        h16, w116, nullptr, ffn16, NTOK, FFND, EMB, 0, 0, 0);

    // 11) out = x2 + ffn @ W2^T (fp32 residual) : M=8192, N=768, K=3072
    gemm_h<128,128,2,4,EPI_RES,false,false><<<dim3(EMB/128, NTOK/128, 1), 256, SM_NT>>>(
        ffn16, w216, x2, out, NTOK, EMB, FFND, 0, 0, 0);
}

// round 9
// speedup vs baseline: 7.9702x; 1.2927x over previous
#include <cuda_runtime.h>
#include <cuda_fp16.h>
#include <math.h>
#include <stdint.h>

// ---------------------------------------------------------------------------
// Problem constants
// ---------------------------------------------------------------------------
#define Bsz   8
#define Tseq  1024
#define EMB   768
#define NH    12
#define HD    64
#define NTOK  (Bsz * Tseq)          // 8192
#define FFND  (4 * EMB)             // 3072

// ---------------------------------------------------------------------------
// Scratch (device globals — allocation-free)
// ---------------------------------------------------------------------------
__device__ __half g_h16  [NTOK * EMB];                 // LN output (fp16)
__device__ __half g_qkv16[3L * NTOK * EMB];            // q|k|v, each [B,H,T,D]
__device__ __half g_ctx16[NTOK * EMB];                 // [B,T,E]
__device__ __half g_ffn16[NTOK * FFND];                // gelu(h @ W1^T)
__device__ float  g_x2   [NTOK * EMB];                 // fp32 residual stream
// fp16 weight copies
__device__ __half g_wqkv16[3 * EMB * EMB];             // wq|wk|wv rows
__device__ __half g_wo16[EMB * EMB];
__device__ __half g_w116[FFND * EMB];
__device__ __half g_w216[EMB * FFND];

// ---------------------------------------------------------------------------
// PTX helpers
// ---------------------------------------------------------------------------
__device__ __forceinline__ void cp16s(uint32_t dst, const void* src) {
    asm volatile("cp.async.ca.shared.global [%0], [%1], 16;" :: "r"(dst), "l"(src));
}
__device__ __forceinline__ void cp_commit() {
    asm volatile("cp.async.commit_group;" ::: "memory");
}
template<int N>
__device__ __forceinline__ void cp_wait() {
    asm volatile("cp.async.wait_group %0;" :: "n"(N) : "memory");
}
__device__ __forceinline__ uint32_t sw128(uint32_t o) {   // Swizzle<3,4,3>, 128B rows
    return o ^ ((o >> 3) & 0x70);
}
__device__ __forceinline__ uint32_t h2_u32(__half2 h) {
    return *reinterpret_cast<uint32_t*>(&h);
}
__device__ __forceinline__ void ldsm4(uint32_t* r, uint32_t addr) {
    asm volatile("ldmatrix.sync.aligned.m8n8.x4.shared.b16 {%0,%1,%2,%3}, [%4];"
        : "=r"(r[0]), "=r"(r[1]), "=r"(r[2]), "=r"(r[3]) : "r"(addr));
}
__device__ __forceinline__ void ldsm4t(uint32_t* r, uint32_t addr) {
    asm volatile("ldmatrix.sync.aligned.m8n8.x4.trans.shared.b16 {%0,%1,%2,%3}, [%4];"
        : "=r"(r[0]), "=r"(r[1]), "=r"(r[2]), "=r"(r[3]) : "r"(addr));
}
__device__ __forceinline__ void mma16816(float* d, const uint32_t* a, const uint32_t* b) {
    asm volatile(
        "mma.sync.aligned.m16n8k16.row.col.f32.f16.f16.f32 "
        "{%0,%1,%2,%3}, {%4,%5,%6,%7}, {%8,%9}, {%0,%1,%2,%3};"
        : "+f"(d[0]), "+f"(d[1]), "+f"(d[2]), "+f"(d[3])
        : "r"(a[0]), "r"(a[1]), "r"(a[2]), "r"(a[3]), "r"(b[0]), "r"(b[1]));
}

// ---------------------------------------------------------------------------
// Block reduction helpers (blockDim.x == 256)
// ---------------------------------------------------------------------------
__device__ __forceinline__ float blk_sum(float v, float* s) {
    int t = threadIdx.x;
    #pragma unroll
    for (int o = 16; o; o >>= 1) v += __shfl_xor_sync(0xffffffffu, v, o);
    if ((t & 31) == 0) s[t >> 5] = v;
    __syncthreads();
    if (t < 32) {
        float w = (t < 8) ? s[t] : 0.0f;
        #pragma unroll
        for (int o = 4; o; o >>= 1) w += __shfl_xor_sync(0xffffffffu, w, o);
        if (t == 0) s[0] = w;
    }
    __syncthreads();
    float r = s[0];
    __syncthreads();
    return r;
}

// ---------------------------------------------------------------------------
// fp32 -> fp16 converter (weights). n % 1024 == 0.
// ---------------------------------------------------------------------------
__global__ void f2h_k(const float* __restrict__ s, __half* __restrict__ d) {
    int i = (blockIdx.x * 256 + threadIdx.x) * 4;
    float4 v = *(const float4*)(s + i);
    *(__half2*)(d + i)     = __floats2half2_rn(v.x, v.y);
    *(__half2*)(d + i + 2) = __floats2half2_rn(v.z, v.w);
}

// ---------------------------------------------------------------------------
// LayerNorm: fp32 in, fp16 out. One block per row of 768.
// ---------------------------------------------------------------------------
__global__ void layernorm_k(const float* __restrict__ x, __half* __restrict__ o,
                            const float* __restrict__ sc, const float* __restrict__ sh) {
    __shared__ float red[32];
    long row = blockIdx.x;
    const float* p = x + row * EMB;
    __half* q = o + row * EMB;
    int t = threadIdx.x;
    float a0 = p[t], a1 = p[t + 256], a2 = p[t + 512];
    float mean = blk_sum(a0 + a1 + a2, red) * (1.0f / EMB);
    float d0 = a0 - mean, d1 = a1 - mean, d2 = a2 - mean;
    float var = blk_sum(d0 * d0 + d1 * d1 + d2 * d2, red) * (1.0f / EMB);
    float rstd = rsqrtf(var + 1e-5f);
    q[t      ] = __float2half_rn(d0 * rstd * sc[t      ] + sh[t      ]);
    q[t + 256] = __float2half_rn(d1 * rstd * sc[t + 256] + sh[t + 256]);
    q[t + 512] = __float2half_rn(d2 * rstd * sc[t + 512] + sh[t + 512]);
}

// ---------------------------------------------------------------------------
// Flash attention: fused QK^T -> causal online softmax -> @V.
// Grid (8 q-tiles, B*NH). 256 threads = 8 warps; warp w owns q rows
// [qt*128 + w*16, +16). K/V tiles of 64 rows, 3-slot cp.async ring
// (prefetch distance 2 — slot disjoint from consumed + previous slots).
// Output ctx fp16 [B,T,E].
// ---------------------------------------------------------------------------
__global__ void __launch_bounds__(256, 2)
flash_k(const __half* __restrict__ Qg, const __half* __restrict__ Kg,
        const __half* __restrict__ Vg, __half* __restrict__ O) {
    const int qt  = blockIdx.x;
    const int bh  = blockIdx.y;
    const int row0 = qt * 128;
    const int b = bh / NH, hh = bh % NH;

    extern __shared__ char smraw[];
    const uint32_t smQ = (uint32_t)__cvta_generic_to_shared(smraw);   // 16 KB
    const uint32_t smK = smQ + 128 * 128;                             // 3 x 8 KB
    const uint32_t smV = smK + 3 * 64 * 128;                          // 3 x 8 KB

    const int tid = threadIdx.x, lane = tid & 31, w = tid >> 5;
    const int g = lane >> 2, tig = lane & 3;
    const int aRow = (lane & 7) + ((lane >> 3) & 1) * 8, aChk = lane >> 4;
    const int bRow = (lane & 7) + (lane >> 4) * 8,       bChk = (lane >> 3) & 1;

    const __half* Qb = Qg + ((long)bh << 10) * HD;
    const __half* Kb = Kg + ((long)bh << 10) * HD;
    const __half* Vb = Vg + ((long)bh << 10) * HD;

    // Q tile: 128 rows x 128B
    for (int i = tid; i < 128 * 8; i += 256) {
        int r = i >> 3, c = i & 7;
        cp16s(smQ + sw128(r * 128 + c * 16), Qb + (long)(row0 + r) * HD + c * 8);
    }
    cp_commit();

    const int nkv = 2 * qt + 2;
    auto load_kv = [&](int it, int s) {
        int kv0 = it * 64;
        #pragma unroll
        for (int i = 0; i < 2; i++) {
            int idx = tid + i * 256, r = idx >> 3, c = idx & 7;
            cp16s(smK + s * 8192 + sw128(r * 128 + c * 16), Kb + (long)(kv0 + r) * HD + c * 8);
        }
        #pragma unroll
        for (int i = 0; i < 2; i++) {
            int idx = tid + i * 256, r = idx >> 3, c = idx & 7;
            cp16s(smV + s * 8192 + sw128(r * 128 + c * 16), Vb + (long)(kv0 + r) * HD + c * 8);
        }
        cp_commit();
    };
    load_kv(0, 0);
    load_kv(1, 1);   // nkv >= 2 always

    // wait for Q (leave the two K/V groups pending), extract Q fragments
    cp_wait<2>();
    __syncthreads();
    uint32_t qf[4][4];
    #pragma unroll
    for (int kc = 0; kc < 4; kc++)
        ldsm4(qf[kc], smQ + sw128((w * 16 + aRow) * 128 + (kc * 2 + aChk) * 16));

    float oacc[8][4] = {};
    float m0 = -INFINITY, m1 = -INFINITY, l0 = 0.0f, l1 = 0.0f;
    const int r0g = row0 + w * 16 + g;      // row of half 0
    const int r1g = r0g + 8;                // row of half 1

    for (int it = 0; it < nkv; it++) {
        int s = it % 3;
        if (it + 2 < nkv) load_kv(it + 2, (it + 2) % 3); else cp_commit();
        cp_wait<2>();
        __syncthreads();

        uint32_t kS = smK + s * 8192, vS = smV + s * 8192;

        // ---- S = Q K^T  (128x64 per CTA; this warp: 16x64) ----
        float sacc[8][4] = {};
        #pragma unroll
        for (int kc = 0; kc < 4; kc++) {
            uint32_t bfr[8][2];
            #pragma unroll
            for (int j = 0; j < 4; j++) {
                uint32_t r4[4];
                ldsm4(r4, kS + sw128((j * 16 + bRow) * 128 + (kc * 2 + bChk) * 16));
                bfr[2*j][0] = r4[0]; bfr[2*j][1] = r4[1];
                bfr[2*j+1][0] = r4[2]; bfr[2*j+1][1] = r4[3];
            }
            #pragma unroll
            for (int ni = 0; ni < 8; ni++)
                mma16816(sacc[ni], qf[kc], bfr[ni]);
        }

        // ---- scale + causal mask + online softmax ----
        const int kv0 = it * 64;
        const bool needmask = (kv0 + 63) > (row0 + w * 16);
        float tm0 = -INFINITY, tm1 = -INFINITY;
        #pragma unroll
        for (int ni = 0; ni < 8; ni++) {
            float s0 = sacc[ni][0] * 0.125f, s1 = sacc[ni][1] * 0.125f;
            float s2 = sacc[ni][2] * 0.125f, s3 = sacc[ni][3] * 0.125f;
            if (needmask) {
                int col = kv0 + ni * 8 + tig * 2;
                if (col     > r0g) s0 = -1e30f;
                if (col + 1 > r0g) s1 = -1e30f;
                if (col     > r1g) s2 = -1e30f;
                if (col + 1 > r1g) s3 = -1e30f;
            }
            sacc[ni][0] = s0; sacc[ni][1] = s1; sacc[ni][2] = s2; sacc[ni][3] = s3;
            tm0 = fmaxf(tm0, fmaxf(s0, s1));
            tm1 = fmaxf(tm1, fmaxf(s2, s3));
        }
        #pragma unroll
        for (int o = 1; o <= 2; o <<= 1) {
            tm0 = fmaxf(tm0, __shfl_xor_sync(0xffffffffu, tm0, o));
            tm1 = fmaxf(tm1, __shfl_xor_sync(0xffffffffu, tm1, o));
        }
        float mn0 = fmaxf(m0, tm0), mn1 = fmaxf(m1, tm1);
        float f0 = __expf(m0 - mn0), f1 = __expf(m1 - mn1);
        m0 = mn0; m1 = mn1;

        uint32_t ph[8][2];
        float ls0 = 0.0f, ls1 = 0.0f;
        #pragma unroll
        for (int ni = 0; ni < 8; ni++) {
            float p0 = __expf(sacc[ni][0] - mn0), p1 = __expf(sacc[ni][1] - mn0);
            float p2 = __expf(sacc[ni][2] - mn1), p3 = __expf(sacc[ni][3] - mn1);
            ls0 += p0 + p1; ls1 += p2 + p3;
            ph[ni][0] = h2_u32(__floats2half2_rn(p0, p1));
            ph[ni][1] = h2_u32(__floats2half2_rn(p2, p3));
        }
        l0 = l0 * f0 + ls0;
        l1 = l1 * f1 + ls1;
        #pragma unroll
        for (int ni = 0; ni < 8; ni++) {
            oacc[ni][0] *= f0; oacc[ni][1] *= f0;
            oacc[ni][2] *= f1; oacc[ni][3] *= f1;
        }

        // ---- O += P @ V ----
        #pragma unroll
        for (int kc = 0; kc < 4; kc++) {
            uint32_t a[4] = { ph[2*kc][0], ph[2*kc][1], ph[2*kc+1][0], ph[2*kc+1][1] };
            uint32_t vb[8][2];
            #pragma unroll
            for (int j = 0; j < 4; j++) {
                uint32_t r4[4];
                ldsm4t(r4, vS + sw128((kc * 16 + aRow) * 128 + (2 * j + aChk) * 16));
                vb[2*j][0] = r4[0]; vb[2*j][1] = r4[1];
                vb[2*j+1][0] = r4[2]; vb[2*j+1][1] = r4[3];
            }
            #pragma unroll
            for (int nj = 0; nj < 8; nj++)
                mma16816(oacc[nj], a, vb[nj]);
        }
        __syncthreads();
    }

    // ---- finalize: divide by row sums, write ctx [B,T,E] ----
    #pragma unroll
    for (int o = 1; o <= 2; o <<= 1) {
        l0 += __shfl_xor_sync(0xffffffffu, l0, o);
        l1 += __shfl_xor_sync(0xffffffffu, l1, o);
    }
    float i0 = 1.0f / l0, i1 = 1.0f / l1;
    __half* Ob = O + ((long)(b << 10)) * EMB;
    #pragma unroll
    for (int ni = 0; ni < 8; ni++) {
        int col = hh * HD + ni * 8 + tig * 2;
        *(__half2*)&Ob[(long)r0g * EMB + col] = __floats2half2_rn(oacc[ni][0] * i0, oacc[ni][1] * i0);
        *(__half2*)&Ob[(long)r1g * EMB + col] = __floats2half2_rn(oacc[ni][2] * i1, oacc[ni][3] * i1);
    }
}

// ---------------------------------------------------------------------------
// fp16 tensor-core GEMM (m16n8k16, ldmatrix, SW128, 3-stage cp.async), NT:
//   C[m,n] = sum_k A[m,k] * B[n,k].  256 threads = 8 warps, 2 CTAs/SM.
// ---------------------------------------------------------------------------
#define EPI_QKV3   0
#define EPI_RES    5
#define EPI_GELU   6

template<int BM, int BN, int WM, int WN, int EPI>
__global__ void __launch_bounds__(256, 2)
gemm_h(const __half* __restrict__ A, const __half* __restrict__ Bm,
       const float* __restrict__ R, void* __restrict__ Cv,
       int M, int N, int K) {
    constexpr int BK  = 64;
    constexpr int WTM = BM / WM, WTN = BN / WN;
    constexpr int MF  = WTM / 16, NF = WTN / 8;
    constexpr int A_STG = BM * BK * 2;
    constexpr int B_STG = BN * BK * 2;

    const int tid  = threadIdx.x;
    const int row0 = blockIdx.y * BM;
    const int col0 = blockIdx.x * BN;

    extern __shared__ char smraw[];
    const uint32_t smA = (uint32_t)__cvta_generic_to_shared(smraw);
    const uint32_t smB = smA + 3 * A_STG;

    auto load_tile = [&](int k0, int s) {
        uint32_t aB = smA + s * A_STG;
        #pragma unroll
        for (int i = 0; i < BM * 8 / 256; i++) {
            int idx = tid + i * 256, r = idx >> 3, c = idx & 7;
            cp16s(aB + sw128(r * 128 + c * 16), A + (long)(row0 + r) * K + k0 + c * 8);
        }
        uint32_t bB = smB + s * B_STG;
        #pragma unroll
        for (int i = 0; i < BN * 8 / 256; i++) {
            int idx = tid + i * 256, r = idx >> 3, c = idx & 7;
            cp16s(bB + sw128(r * 128 + c * 16), Bm + (long)(col0 + r) * K + k0 + c * 8);
        }
        cp_commit();
    };

    const int lane = tid & 31, w = tid >> 5;
    const int g = lane >> 2, tig = lane & 3;
    const int rw = (w % WM) * WTM, cw = (w / WM) * WTN;
    const int aRow = (lane & 7) + ((lane >> 3) & 1) * 8, aChk = lane >> 4;
    const int bRow = (lane & 7) + (lane >> 4) * 8,       bChk = (lane >> 3) & 1;

    float acc[MF][NF][4] = {};

    const int nt = K / BK;
    load_tile(0, 0);
    if (nt > 1) load_tile(BK, 1); else cp_commit();

    for (int it = 0; it < nt; it++) {
        int s = it % 3;
        if (it + 2 < nt) load_tile((it + 2) * BK, (it + 2) % 3); else cp_commit();
        cp_wait<2>();
        __syncthreads();
        uint32_t aS = smA + s * A_STG, bS = smB + s * B_STG;

        #pragma unroll
        for (int kk = 0; kk < BK; kk += 16) {
            uint32_t afr[MF][4];
            #pragma unroll
            for (int mi = 0; mi < MF; mi++)
                ldsm4(afr[mi], aS + sw128((rw + mi * 16 + aRow) * 128 + ((kk >> 3) + aChk) * 16));
            uint32_t bfr[NF][2];
            #pragma unroll
            for (int j = 0; j < NF / 2; j++) {
                uint32_t r4[4];
                ldsm4(r4, bS + sw128((cw + j * 16 + bRow) * 128 + ((kk >> 3) + bChk) * 16));
                bfr[2*j][0] = r4[0]; bfr[2*j][1] = r4[1];
                bfr[2*j+1][0] = r4[2]; bfr[2*j+1][1] = r4[3];
            }
            #pragma unroll
            for (int mi = 0; mi < MF; mi++)
                #pragma unroll
                for (int ni = 0; ni < NF; ni++)
                    mma16816(acc[mi][ni], afr[mi], bfr[ni]);
        }
        __syncthreads();
    }

    // ---------------- epilogue ----------------
    #pragma unroll
    for (int mi = 0; mi < MF; mi++) {
        #pragma unroll
        for (int ni = 0; ni < NF; ni++) {
            int r_ = row0 + rw + mi * 16 + g;
            int c_ = col0 + cw + ni * 8 + tig * 2;
            float* a4 = acc[mi][ni];
            #pragma unroll
            for (int half = 0; half < 2; half++) {
                int rr = r_ + half * 8;
                float v0 = a4[half * 2 + 0];
                float v1 = a4[half * 2 + 1];

                if (EPI == EPI_QKV3) {
                    // c_ in [0,2304): segment 0/1/2 -> q/k/v buffers (contiguous)
                    __half* Cp = (__half*)Cv;
                    int seg = c_ / EMB;
                    int cn  = c_ - seg * EMB;
                    int b = rr >> 10, t = rr & 1023;
                    int h = cn >> 6,  d = cn & 63;
                    long o = (long)seg * (NTOK * EMB)
                           + (((long)(b * NH + h) << 10) + t) * HD + d;
                    *(__half2*)&Cp[o] = __floats2half2_rn(v0, v1);
                } else if (EPI == EPI_RES) {
                    float* Cp = (float*)Cv;
                    long o = (long)rr * N + c_;
                    float2 rv = *(const float2*)&R[o];
                    *(float2*)&Cp[o] = make_float2(v0 + rv.x, v1 + rv.y);
                } else if (EPI == EPI_GELU) {
                    __half* Cp = (__half*)Cv;
                    const float cst = 0.7978845608028654f;
                    float gl0 = 0.5f * v0 * (1.0f + tanhf(cst * (v0 + 0.044715f * v0 * v0 * v0)));
                    float gl1 = 0.5f * v1 * (1.0f + tanhf(cst * (v1 + 0.044715f * v1 * v1 * v1)));
                    *(__half2*)&Cp[(long)rr * N + c_] = __floats2half2_rn(gl0, gl1);
                }
            }
        }
    }
}

// ---------------------------------------------------------------------------
// Launch
// ---------------------------------------------------------------------------
extern "C" void kernel_launch(void* const* d_in, const int* in_sizes, int n_in,
                              void* d_out, int out_size) {
    const float* x    = (const float*)d_in[0];
    const float* wq   = (const float*)d_in[1];
    const float* wk   = (const float*)d_in[2];
    const float* wv   = (const float*)d_in[3];
    const float* wo   = (const float*)d_in[4];
    const float* w1   = (const float*)d_in[5];
    const float* w2   = (const float*)d_in[6];
    const float* ln1s = (const float*)d_in[7];
    const float* ln1b = (const float*)d_in[8];
    const float* ln2s = (const float*)d_in[9];
    const float* ln2b = (const float*)d_in[10];
    float* out = (float*)d_out;

    __half *h16, *qkv16, *ctx16, *ffn16, *wqkv16, *wo16, *w116, *w216;
    float* x2;
    cudaGetSymbolAddress((void**)&h16,    g_h16);
    cudaGetSymbolAddress((void**)&qkv16,  g_qkv16);
    cudaGetSymbolAddress((void**)&ctx16,  g_ctx16);
    cudaGetSymbolAddress((void**)&ffn16,  g_ffn16);
    cudaGetSymbolAddress((void**)&x2,     g_x2);
    cudaGetSymbolAddress((void**)&wqkv16, g_wqkv16);
    cudaGetSymbolAddress((void**)&wo16,   g_wo16);
    cudaGetSymbolAddress((void**)&w116,   g_w116);
    cudaGetSymbolAddress((void**)&w216,   g_w216);

    __half* q16 = qkv16;
    __half* k16 = qkv16 + (long)NTOK * EMB;
    __half* v16 = qkv16 + 2L * NTOK * EMB;

    constexpr int SM_NT    = 3 * (128 * 64 + 128 * 64) * 2;   // 98304 B
    constexpr int SM_FLASH = 128 * 128 + 2 * 3 * 64 * 128 * 2; // 16K + 48K = 65536 B

    cudaFuncSetAttribute(gemm_h<128,128,2,4,EPI_QKV3>,
                         cudaFuncAttributeMaxDynamicSharedMemorySize, SM_NT);
    cudaFuncSetAttribute(gemm_h<128,128,2,4,EPI_RES>,
                         cudaFuncAttributeMaxDynamicSharedMemorySize, SM_NT);
    cudaFuncSetAttribute(gemm_h<128,128,2,4,EPI_GELU>,
                         cudaFuncAttributeMaxDynamicSharedMemorySize, SM_NT);
    cudaFuncSetAttribute(flash_k,
                         cudaFuncAttributeMaxDynamicSharedMemorySize, SM_FLASH);

    // 0) weight fp32 -> fp16 (wq|wk|wv fused into one [2304,768] buffer)
    f2h_k<<<EMB * EMB / 1024, 256>>>(wq, wqkv16);
    f2h_k<<<EMB * EMB / 1024, 256>>>(wk, wqkv16 + EMB * EMB);
    f2h_k<<<EMB * EMB / 1024, 256>>>(wv, wqkv16 + 2 * EMB * EMB);
    f2h_k<<<EMB * EMB / 1024, 256>>>(wo, wo16);
    f2h_k<<<FFND * EMB / 1024, 256>>>(w1, w116);
    f2h_k<<<EMB * FFND / 1024, 256>>>(w2, w216);

    // 1) LN1 (fp32 -> fp16)
    layernorm_k<<<NTOK, 256>>>(x, h16, ln1s, ln1b);

    // 2) fused QKV projection : M=8192, N=2304, K=768 -> q|k|v [B,H,T,D]
    gemm_h<128,128,2,4,EPI_QKV3><<<dim3(3 * EMB / 128, NTOK / 128), 256, SM_NT>>>(
        h16, wqkv16, nullptr, qkv16, NTOK, 3 * EMB, EMB);

    // 3) flash attention -> ctx fp16 [B,T,E]
    flash_k<<<dim3(Tseq / 128, Bsz * NH), 256, SM_FLASH>>>(q16, k16, v16, ctx16);

    // 4) x2 = x + ctx @ Wo^T (fp32 residual) : M=8192, N=768, K=768
    gemm_h<128,128,2,4,EPI_RES><<<dim3(EMB / 128, NTOK / 128), 256, SM_NT>>>(
        ctx16, wo16, x, x2, NTOK, EMB, EMB);

    // 5) LN2 (fp32 -> fp16)
    layernorm_k<<<NTOK, 256>>>(x2, h16, ln2s, ln2b);

    // 6) ffn = gelu(h @ W1^T) fp16 : M=8192, N=3072, K=768
    gemm_h<128,128,2,4,EPI_GELU><<<dim3(FFND / 128, NTOK / 128), 256, SM_NT>>>(
        h16, w116, nullptr, ffn16, NTOK, FFND, EMB);

    // 7) out = x2 + ffn @ W2^T (fp32 residual) : M=8192, N=768, K=3072
    gemm_h<128,128,2,4,EPI_RES><<<dim3(EMB / 128, NTOK / 128), 256, SM_NT>>>(
        ffn16, w216, x2, out, NTOK, EMB, FFND);
}

// round 11
// speedup vs baseline: 8.1557x; 1.0233x over previous
#include <cuda_runtime.h>
#include <cuda_fp16.h>
#include <math.h>
#include <stdint.h>

// ---------------------------------------------------------------------------
// Problem constants
// ---------------------------------------------------------------------------
#define Bsz   8
#define Tseq  1024
#define EMB   768
#define NH    12
#define HD    64
#define NTOK  (Bsz * Tseq)          // 8192
#define FFND  (4 * EMB)             // 3072

// ---------------------------------------------------------------------------
// Scratch (device globals — allocation-free)
// ---------------------------------------------------------------------------
__device__ __half g_h16  [NTOK * EMB];                 // LN output (fp16)
__device__ __half g_qkv16[3L * NTOK * EMB];            // q|k|v, each [B,H,T,D]
__device__ __half g_ctx16[NTOK * EMB];                 // [B,T,E]
__device__ __half g_ffn16[NTOK * FFND];                // gelu(h @ W1^T)
__device__ float  g_x2   [NTOK * EMB];                 // fp32 residual stream
// fp16 weight copies
__device__ __half g_wqkv16[3 * EMB * EMB];             // wq|wk|wv rows
__device__ __half g_wo16[EMB * EMB];
__device__ __half g_w116[FFND * EMB];
__device__ __half g_w216[EMB * FFND];

// ---------------------------------------------------------------------------
// PTX helpers
// ---------------------------------------------------------------------------
__device__ __forceinline__ void cp16s(uint32_t dst, const void* src) {
    asm volatile("cp.async.ca.shared.global [%0], [%1], 16;" :: "r"(dst), "l"(src));
}
__device__ __forceinline__ void cp_commit() {
    asm volatile("cp.async.commit_group;" ::: "memory");
}
template<int N>
__device__ __forceinline__ void cp_wait() {
    asm volatile("cp.async.wait_group %0;" :: "n"(N) : "memory");
}
__device__ __forceinline__ uint32_t sw128(uint32_t o) {   // Swizzle<3,4,3>, 128B rows
    return o ^ ((o >> 3) & 0x70);
}
__device__ __forceinline__ uint32_t h2_u32(__half2 h) {
    return *reinterpret_cast<uint32_t*>(&h);
}
__device__ __forceinline__ void ldsm4(uint32_t* r, uint32_t addr) {
    asm volatile("ldmatrix.sync.aligned.m8n8.x4.shared.b16 {%0,%1,%2,%3}, [%4];"
        : "=r"(r[0]), "=r"(r[1]), "=r"(r[2]), "=r"(r[3]) : "r"(addr));
}
__device__ __forceinline__ void ldsm4t(uint32_t* r, uint32_t addr) {
    asm volatile("ldmatrix.sync.aligned.m8n8.x4.trans.shared.b16 {%0,%1,%2,%3}, [%4];"
        : "=r"(r[0]), "=r"(r[1]), "=r"(r[2]), "=r"(r[3]) : "r"(addr));
}
__device__ __forceinline__ void mma16816(float* d, const uint32_t* a, const uint32_t* b) {
    asm volatile(
        "mma.sync.aligned.m16n8k16.row.col.f32.f16.f16.f32 "
        "{%0,%1,%2,%3}, {%4,%5,%6,%7}, {%8,%9}, {%0,%1,%2,%3};"
        : "+f"(d[0]), "+f"(d[1]), "+f"(d[2]), "+f"(d[3])
        : "r"(a[0]), "r"(a[1]), "r"(a[2]), "r"(a[3]), "r"(b[0]), "r"(b[1]));
}

// ---------------------------------------------------------------------------
// Block reduction helper (blockDim.x == 256)
// ---------------------------------------------------------------------------
__device__ __forceinline__ float blk_sum(float v, float* s) {
    int t = threadIdx.x;
    #pragma unroll
    for (int o = 16; o; o >>= 1) v += __shfl_xor_sync(0xffffffffu, v, o);
    if ((t & 31) == 0) s[t >> 5] = v;
    __syncthreads();
    if (t < 32) {
        float w = (t < 8) ? s[t] : 0.0f;
        #pragma unroll
        for (int o = 4; o; o >>= 1) w += __shfl_xor_sync(0xffffffffu, w, o);
        if (t == 0) s[0] = w;
    }
    __syncthreads();
    float r = s[0];
    __syncthreads();
    return r;
}

// ---------------------------------------------------------------------------
// Merged fp32 -> fp16 weight converter. blockIdx.y selects segment.
// Segment sizes: 0-3 = EMB*EMB (576 blocks), 4-5 = FFND*EMB (2304 blocks).
// ---------------------------------------------------------------------------
__global__ void f2h_all_k(const float* __restrict__ wq, const float* __restrict__ wk,
                          const float* __restrict__ wv, const float* __restrict__ wo,
                          const float* __restrict__ w1, const float* __restrict__ w2,
                          __half* __restrict__ dqkv, __half* __restrict__ dwo,
                          __half* __restrict__ dw1, __half* __restrict__ dw2) {
    const int seg = blockIdx.y;
    const int nblk = (seg < 4) ? (EMB * EMB / 1024) : (FFND * EMB / 1024);
    if (blockIdx.x >= nblk) return;
    const float* s;
    __half* d;
    switch (seg) {
        case 0: s = wq; d = dqkv;                 break;
        case 1: s = wk; d = dqkv + EMB * EMB;     break;
        case 2: s = wv; d = dqkv + 2 * EMB * EMB; break;
        case 3: s = wo; d = dwo;                  break;
        case 4: s = w1; d = dw1;                  break;
        default: s = w2; d = dw2;                 break;
    }
    int i = (blockIdx.x * 256 + threadIdx.x) * 4;
    float4 v = *(const float4*)(s + i);
    *(__half2*)(d + i)     = __floats2half2_rn(v.x, v.y);
    *(__half2*)(d + i + 2) = __floats2half2_rn(v.z, v.w);
}

// ---------------------------------------------------------------------------
// LayerNorm: fp32 in, fp16 out. One block per row of 768.
// ---------------------------------------------------------------------------
__global__ void layernorm_k(const float* __restrict__ x, __half* __restrict__ o,
                            const float* __restrict__ sc, const float* __restrict__ sh) {
    __shared__ float red[32];
    long row = blockIdx.x;
    const float* p = x + row * EMB;
    __half* q = o + row * EMB;
    int t = threadIdx.x;
    float a0 = p[t], a1 = p[t + 256], a2 = p[t + 512];
    float mean = blk_sum(a0 + a1 + a2, red) * (1.0f / EMB);
    float d0 = a0 - mean, d1 = a1 - mean, d2 = a2 - mean;
    float var = blk_sum(d0 * d0 + d1 * d1 + d2 * d2, red) * (1.0f / EMB);
    float rstd = rsqrtf(var + 1e-5f);
    q[t      ] = __float2half_rn(d0 * rstd * sc[t      ] + sh[t      ]);
    q[t + 256] = __float2half_rn(d1 * rstd * sc[t + 256] + sh[t + 256]);
    q[t + 512] = __float2half_rn(d2 * rstd * sc[t + 512] + sh[t + 512]);
}

// ---------------------------------------------------------------------------
// Flash attention: fused QK^T -> causal online softmax -> @V.
// Grid (8 q-tiles heavy-first, B*NH). 256 threads = 8 warps; warp w owns q
// rows [qt*128 + w*16, +16). K/V tiles of 64 rows, 3-slot cp.async ring.
// ---------------------------------------------------------------------------
__global__ void __launch_bounds__(256, 2)
flash_k(const __half* __restrict__ Qg, const __half* __restrict__ Kg,
        const __half* __restrict__ Vg, __half* __restrict__ O) {
    const int qt  = gridDim.x - 1 - blockIdx.x;     // heavy tiles first
    const int bh  = blockIdx.y;
    const int row0 = qt * 128;
    const int b = bh / NH, hh = bh % NH;

    extern __shared__ char smraw[];
    const uint32_t smQ = (uint32_t)__cvta_generic_to_shared(smraw);   // 16 KB
    const uint32_t smK = smQ + 128 * 128;                             // 3 x 8 KB
    const uint32_t smV = smK + 3 * 64 * 128;                          // 3 x 8 KB

    const int tid = threadIdx.x, lane = tid & 31, w = tid >> 5;
    const int g = lane >> 2, tig = lane & 3;
    const int aRow = (lane & 7) + ((lane >> 3) & 1) * 8, aChk = lane >> 4;
    const int bRow = (lane & 7) + (lane >> 4) * 8,       bChk = (lane >> 3) & 1;

    const __half* Qb = Qg + ((long)bh << 10) * HD;
    const __half* Kb = Kg + ((long)bh << 10) * HD;
    const __half* Vb = Vg + ((long)bh << 10) * HD;

    for (int i = tid; i < 128 * 8; i += 256) {
        int r = i >> 3, c = i & 7;
        cp16s(smQ + sw128(r * 128 + c * 16), Qb + (long)(row0 + r) * HD + c * 8);
    }
    cp_commit();

    const int nkv = 2 * qt + 2;
    auto load_kv = [&](int it, int s) {
        int kv0 = it * 64;
        #pragma unroll
        for (int i = 0; i < 2; i++) {
            int idx = tid + i * 256, r = idx >> 3, c = idx & 7;
            cp16s(smK + s * 8192 + sw128(r * 128 + c * 16), Kb + (long)(kv0 + r) * HD + c * 8);
        }
        #pragma unroll
        for (int i = 0; i < 2; i++) {
            int idx = tid + i * 256, r = idx >> 3, c = idx & 7;
            cp16s(smV + s * 8192 + sw128(r * 128 + c * 16), Vb + (long)(kv0 + r) * HD + c * 8);
        }
        cp_commit();
    };
    load_kv(0, 0);
    load_kv(1, 1);   // nkv >= 2 always

    cp_wait<2>();
    __syncthreads();
    uint32_t qf[4][4];
    #pragma unroll
    for (int kc = 0; kc < 4; kc++)
        ldsm4(qf[kc], smQ + sw128((w * 16 + aRow) * 128 + (kc * 2 + aChk) * 16));

    float oacc[8][4] = {};
    float m0 = -INFINITY, m1 = -INFINITY, l0 = 0.0f, l1 = 0.0f;
    const int r0g = row0 + w * 16 + g;
    const int r1g = r0g + 8;

    for (int it = 0; it < nkv; it++) {
        int s = it % 3;
        if (it + 2 < nkv) load_kv(it + 2, (it + 2) % 3); else cp_commit();
        cp_wait<2>();
        __syncthreads();

        uint32_t kS = smK + s * 8192, vS = smV + s * 8192;

        // ---- S = Q K^T ----
        float sacc[8][4] = {};
        #pragma unroll
        for (int kc = 0; kc < 4; kc++) {
            uint32_t bfr[8][2];
            #pragma unroll
            for (int j = 0; j < 4; j++) {
                uint32_t r4[4];
                ldsm4(r4, kS + sw128((j * 16 + bRow) * 128 + (kc * 2 + bChk) * 16));
                bfr[2*j][0] = r4[0]; bfr[2*j][1] = r4[1];
                bfr[2*j+1][0] = r4[2]; bfr[2*j+1][1] = r4[3];
            }
            #pragma unroll
            for (int ni = 0; ni < 8; ni++)
                mma16816(sacc[ni], qf[kc], bfr[ni]);
        }

        // ---- scale + causal mask + online softmax ----
        const int kv0 = it * 64;
        const bool needmask = (kv0 + 63) > (row0 + w * 16);
        float tm0 = -INFINITY, tm1 = -INFINITY;
        #pragma unroll
        for (int ni = 0; ni < 8; ni++) {
            float s0 = sacc[ni][0] * 0.125f, s1 = sacc[ni][1] * 0.125f;
            float s2 = sacc[ni][2] * 0.125f, s3 = sacc[ni][3] * 0.125f;
            if (needmask) {
                int col = kv0 + ni * 8 + tig * 2;
                if (col     > r0g) s0 = -1e30f;
                if (col + 1 > r0g) s1 = -1e30f;
                if (col     > r1g) s2 = -1e30f;
                if (col + 1 > r1g) s3 = -1e30f;
            }
            sacc[ni][0] = s0; sacc[ni][1] = s1; sacc[ni][2] = s2; sacc[ni][3] = s3;
            tm0 = fmaxf(tm0, fmaxf(s0, s1));
            tm1 = fmaxf(tm1, fmaxf(s2, s3));
        }
        #pragma unroll
        for (int o = 1; o <= 2; o <<= 1) {
            tm0 = fmaxf(tm0, __shfl_xor_sync(0xffffffffu, tm0, o));
            tm1 = fmaxf(tm1, __shfl_xor_sync(0xffffffffu, tm1, o));
        }
        float mn0 = fmaxf(m0, tm0), mn1 = fmaxf(m1, tm1);
        float f0 = __expf(m0 - mn0), f1 = __expf(m1 - mn1);
        m0 = mn0; m1 = mn1;

        uint32_t ph[8][2];
        float ls0 = 0.0f, ls1 = 0.0f;
        #pragma unroll
        for (int ni = 0; ni < 8; ni++) {
            float p0 = __expf(sacc[ni][0] - mn0), p1 = __expf(sacc[ni][1] - mn0);
            float p2 = __expf(sacc[ni][2] - mn1), p3 = __expf(sacc[ni][3] - mn1);
            ls0 += p0 + p1; ls1 += p2 + p3;
            ph[ni][0] = h2_u32(__floats2half2_rn(p0, p1));
            ph[ni][1] = h2_u32(__floats2half2_rn(p2, p3));
        }
        l0 = l0 * f0 + ls0;
        l1 = l1 * f1 + ls1;
        #pragma unroll
        for (int ni = 0; ni < 8; ni++) {
            oacc[ni][0] *= f0; oacc[ni][1] *= f0;
            oacc[ni][2] *= f1; oacc[ni][3] *= f1;
        }

        // ---- O += P @ V ----
        #pragma unroll
        for (int kc = 0; kc < 4; kc++) {
            uint32_t a[4] = { ph[2*kc][0], ph[2*kc][1], ph[2*kc+1][0], ph[2*kc+1][1] };
            uint32_t vb[8][2];
            #pragma unroll
            for (int j = 0; j < 4; j++) {
                uint32_t r4[4];
                ldsm4t(r4, vS + sw128((kc * 16 + aRow) * 128 + (2 * j + aChk) * 16));
                vb[2*j][0] = r4[0]; vb[2*j][1] = r4[1];
                vb[2*j+1][0] = r4[2]; vb[2*j+1][1] = r4[3];
            }
            #pragma unroll
            for (int nj = 0; nj < 8; nj++)
                mma16816(oacc[nj], a, vb[nj]);
        }
        __syncthreads();
    }

    // ---- finalize ----
    #pragma unroll
    for (int o = 1; o <= 2; o <<= 1) {
        l0 += __shfl_xor_sync(0xffffffffu, l0, o);
        l1 += __shfl_xor_sync(0xffffffffu, l1, o);
    }
    float i0 = 1.0f / l0, i1 = 1.0f / l1;
    __half* Ob = O + ((long)(b << 10)) * EMB;
    #pragma unroll
    for (int ni = 0; ni < 8; ni++) {
        int col = hh * HD + ni * 8 + tig * 2;
        *(__half2*)&Ob[(long)r0g * EMB + col] = __floats2half2_rn(oacc[ni][0] * i0, oacc[ni][1] * i0);
        *(__half2*)&Ob[(long)r1g * EMB + col] = __floats2half2_rn(oacc[ni][2] * i1, oacc[ni][3] * i1);
    }
}

// ---------------------------------------------------------------------------
// fp16 tensor-core GEMM (m16n8k16, ldmatrix, SW128, 3-stage cp.async), NT:
//   C[m,n] = sum_k A[m,k] * B[n,k].  256 threads = 8 warps, 2 CTAs/SM.
// ---------------------------------------------------------------------------
#define EPI_QKV3   0
#define EPI_RES    5
#define EPI_GELU   6

template<int BM, int BN, int WM, int WN, int EPI>
__global__ void __launch_bounds__(256, 2)
gemm_h(const __half* __restrict__ A, const __half* __restrict__ Bm,
       const float* __restrict__ R, void* __restrict__ Cv,
       int M, int N, int K) {
    constexpr int BK  = 64;
    constexpr int WTM = BM / WM, WTN = BN / WN;
    constexpr int MF  = WTM / 16, NF = WTN / 8;
    constexpr int A_STG = BM * BK * 2;
    constexpr int B_STG = BN * BK * 2;

    const int tid  = threadIdx.x;
    const int row0 = blockIdx.y * BM;
    const int col0 = blockIdx.x * BN;

    extern __shared__ char smraw[];
    const uint32_t smA = (uint32_t)__cvta_generic_to_shared(smraw);
    const uint32_t smB = smA + 3 * A_STG;

    auto load_tile = [&](int k0, int s) {
        uint32_t aB = smA + s * A_STG;
        #pragma unroll
        for (int i = 0; i < BM * 8 / 256; i++) {
            int idx = tid + i * 256, r = idx >> 3, c = idx & 7;
            cp16s(aB + sw128(r * 128 + c * 16), A + (long)(row0 + r) * K + k0 + c * 8);
        }
        uint32_t bB = smB + s * B_STG;
        #pragma unroll
        for (int i = 0; i < BN * 8 / 256; i++) {
            int idx = tid + i * 256, r = idx >> 3, c = idx & 7;
            cp16s(bB + sw128(r * 128 + c * 16), Bm + (long)(col0 + r) * K + k0 + c * 8);
        }
        cp_commit();
    };

    const int lane = tid & 31, w = tid >> 5;
    const int g = lane >> 2, tig = lane & 3;
    const int rw = (w % WM) * WTM, cw = (w / WM) * WTN;
    const int aRow = (lane & 7) + ((lane >> 3) & 1) * 8, aChk = lane >> 4;
    const int bRow = (lane & 7) + (lane >> 4) * 8,       bChk = (lane >> 3) & 1;

    float acc[MF][NF][4] = {};

    const int nt = K / BK;
    load_tile(0, 0);
    if (nt > 1) load_tile(BK, 1); else cp_commit();

    for (int it = 0; it < nt; it++) {
        int s = it % 3;
        if (it + 2 < nt) load_tile((it + 2) * BK, (it + 2) % 3); else cp_commit();
        cp_wait<2>();
        __syncthreads();
        uint32_t aS = smA + s * A_STG, bS = smB + s * B_STG;

        #pragma unroll
        for (int kk = 0; kk < BK; kk += 16) {
            uint32_t afr[MF][4];
            #pragma unroll
            for (int mi = 0; mi < MF; mi++)
                ldsm4(afr[mi], aS + sw128((rw + mi * 16 + aRow) * 128 + ((kk >> 3) + aChk) * 16));
            uint32_t bfr[NF][2];
            #pragma unroll
            for (int j = 0; j < NF / 2; j++) {
                uint32_t r4[4];
                ldsm4(r4, bS + sw128((cw + j * 16 + bRow) * 128 + ((kk >> 3) + bChk) * 16));
                bfr[2*j][0] = r4[0]; bfr[2*j][1] = r4[1];
                bfr[2*j+1][0] = r4[2]; bfr[2*j+1][1] = r4[3];
            }
            #pragma unroll
            for (int mi = 0; mi < MF; mi++)
                #pragma unroll
                for (int ni = 0; ni < NF; ni++)
                    mma16816(acc[mi][ni], afr[mi], bfr[ni]);
        }
        __syncthreads();
    }

    // ---------------- epilogue ----------------
    #pragma unroll
    for (int mi = 0; mi < MF; mi++) {
        #pragma unroll
        for (int ni = 0; ni < NF; ni++) {
            int r_ = row0 + rw + mi * 16 + g;
            int c_ = col0 + cw + ni * 8 + tig * 2;
            float* a4 = acc[mi][ni];
            #pragma unroll
            for (int half = 0; half < 2; half++) {
                int rr = r_ + half * 8;
                float v0 = a4[half * 2 + 0];
                float v1 = a4[half * 2 + 1];

                if (EPI == EPI_QKV3) {
                    __half* Cp = (__half*)Cv;
                    int seg = c_ / EMB;
                    int cn  = c_ - seg * EMB;
                    int b = rr >> 10, t = rr & 1023;
                    int h = cn >> 6,  d = cn & 63;
                    long o = (long)seg * (NTOK * EMB)
                           + (((long)(b * NH + h) << 10) + t) * HD + d;
                    *(__half2*)&Cp[o] = __floats2half2_rn(v0, v1);
                } else if (EPI == EPI_RES) {
                    float* Cp = (float*)Cv;
                    long o = (long)rr * N + c_;
                    float2 rv = *(const float2*)&R[o];
                    *(float2*)&Cp[o] = make_float2(v0 + rv.x, v1 + rv.y);
                } else if (EPI == EPI_GELU) {
                    __half* Cp = (__half*)Cv;
                    // gelu_tanh(x) = x * sigmoid(2c(x + 0.044715 x^3)), exact identity
                    float y0 = 1.5957691216057308f * (v0 + 0.044715f * v0 * v0 * v0);
                    float y1 = 1.5957691216057308f * (v1 + 0.044715f * v1 * v1 * v1);
                    float g0 = v0 / (1.0f + __expf(-y0));
                    float g1 = v1 / (1.0f + __expf(-y1));
                    *(__half2*)&Cp[(long)rr * N + c_] = __floats2half2_rn(g0, g1);
                }
            }
        }
    }
}

// ---------------------------------------------------------------------------
// Launch
// ---------------------------------------------------------------------------
extern "C" void kernel_launch(void* const* d_in, const int* in_sizes, int n_in,
                              void* d_out, int out_size) {
    const float* x    = (const float*)d_in[0];
    const float* wq   = (const float*)d_in[1];
    const float* wk   = (const float*)d_in[2];
    const float* wv   = (const float*)d_in[3];
    const float* wo   = (const float*)d_in[4];
    const float* w1   = (const float*)d_in[5];
    const float* w2   = (const float*)d_in[6];
    const float* ln1s = (const float*)d_in[7];
    const float* ln1b = (const float*)d_in[8];
    const float* ln2s = (const float*)d_in[9];
    const float* ln2b = (const float*)d_in[10];
    float* out = (float*)d_out;

    __half *h16, *qkv16, *ctx16, *ffn16, *wqkv16, *wo16, *w116, *w216;
    float* x2;
    cudaGetSymbolAddress((void**)&h16,    g_h16);
    cudaGetSymbolAddress((void**)&qkv16,  g_qkv16);
    cudaGetSymbolAddress((void**)&ctx16,  g_ctx16);
    cudaGetSymbolAddress((void**)&ffn16,  g_ffn16);
    cudaGetSymbolAddress((void**)&x2,     g_x2);
    cudaGetSymbolAddress((void**)&wqkv16, g_wqkv16);
    cudaGetSymbolAddress((void**)&wo16,   g_wo16);
    cudaGetSymbolAddress((void**)&w116,   g_w116);
    cudaGetSymbolAddress((void**)&w216,   g_w216);

    __half* q16 = qkv16;
    __half* k16 = qkv16 + (long)NTOK * EMB;
    __half* v16 = qkv16 + 2L * NTOK * EMB;

    constexpr int SM_NT    = 3 * (128 * 64 + 128 * 64) * 2;    // 98304 B
    constexpr int SM_FLASH = 128 * 128 + 2 * 3 * 64 * 128 * 2; // 65536 B

    cudaFuncSetAttribute(gemm_h<128,128,2,4,EPI_QKV3>,
                         cudaFuncAttributeMaxDynamicSharedMemorySize, SM_NT);
    cudaFuncSetAttribute(gemm_h<128,128,2,4,EPI_RES>,
                         cudaFuncAttributeMaxDynamicSharedMemorySize, SM_NT);
    cudaFuncSetAttribute(gemm_h<128,128,2,4,EPI_GELU>,
                         cudaFuncAttributeMaxDynamicSharedMemorySize, SM_NT);
    cudaFuncSetAttribute(flash_k,
                         cudaFuncAttributeMaxDynamicSharedMemorySize, SM_FLASH);

    // 0) all weight fp32 -> fp16 conversions in one launch
    f2h_all_k<<<dim3(FFND * EMB / 1024, 6), 256>>>(
        wq, wk, wv, wo, w1, w2, wqkv16, wo16, w116, w216);

    // 1) LN1 (fp32 -> fp16)
    layernorm_k<<<NTOK, 256>>>(x, h16, ln1s, ln1b);

    // 2) fused QKV projection : M=8192, N=2304, K=768 -> q|k|v [B,H,T,D]
    gemm_h<128,128,2,4,EPI_QKV3><<<dim3(3 * EMB / 128, NTOK / 128), 256, SM_NT>>>(
        h16, wqkv16, nullptr, qkv16, NTOK, 3 * EMB, EMB);

    // 3) flash attention -> ctx fp16 [B,T,E]
    flash_k<<<dim3(Tseq / 128, Bsz * NH), 256, SM_FLASH>>>(q16, k16, v16, ctx16);

    // 4) x2 = x + ctx @ Wo^T (fp32 residual) : M=8192, N=768, K=768
    gemm_h<128,128,2,4,EPI_RES><<<dim3(EMB / 128, NTOK / 128), 256, SM_NT>>>(
        ctx16, wo16, x, x2, NTOK, EMB, EMB);

    // 5) LN2 (fp32 -> fp16)
    layernorm_k<<<NTOK, 256>>>(x2, h16, ln2s, ln2b);

    // 6) ffn = gelu(h @ W1^T) fp16 : M=8192, N=3072, K=768
    gemm_h<128,128,2,4,EPI_GELU><<<dim3(FFND / 128, NTOK / 128), 256, SM_NT>>>(
        h16, w116, nullptr, ffn16, NTOK, FFND, EMB);

    // 7) out = x2 + ffn @ W2^T (fp32 residual) : M=8192, N=768, K=3072
    gemm_h<128,128,2,4,EPI_RES><<<dim3(EMB / 128, NTOK / 128), 256, SM_NT>>>(
        ffn16, w216, x2, out, NTOK, EMB, FFND);
}